// round 12
// baseline (speedup 1.0000x reference)
#include <cuda_runtime.h>
#include <cuda_fp16.h>
#include <math.h>
#include <stdint.h>

#define SEQ 4096
#define DM  1024
#define NH  16
#define DK  64

// ---------------------------------------------------------------------------
// scratch (no allocs allowed) — fp16 hi/lo pairs (V consumed hi-only)
// ---------------------------------------------------------------------------
__device__ __half g_xh [SEQ * DM];
__device__ __half g_xl [SEQ * DM];
__device__ __half g_wh [4][DM * DM];
__device__ __half g_wl [4][DM * DM];
__device__ __half g_qh [NH * SEQ * DK];
__device__ __half g_ql [NH * SEQ * DK];
__device__ __half g_kh [NH * SEQ * DK];
__device__ __half g_kl [NH * SEQ * DK];
__device__ __half g_vh [NH * SEQ * DK];
__device__ __half g_aoh[SEQ * DM];
__device__ __half g_aol[SEQ * DM];

// ---------------------------------------------------------------------------
// helpers
// ---------------------------------------------------------------------------
static __device__ __forceinline__ uint32_t s2u(const void* p) {
    uint32_t a;
    asm("{ .reg .u64 t; cvta.to.shared.u64 t, %1; cvt.u32.u64 %0, t; }"
        : "=r"(a) : "l"(p));
    return a;
}
static __device__ __forceinline__ void ldsm4(uint32_t* r, uint32_t addr) {
    asm volatile("ldmatrix.sync.aligned.m8n8.x4.shared.b16 {%0,%1,%2,%3}, [%4];"
                 : "=r"(r[0]), "=r"(r[1]), "=r"(r[2]), "=r"(r[3]) : "r"(addr));
}
static __device__ __forceinline__ void ldsm4t(uint32_t* r, uint32_t addr) {
    asm volatile("ldmatrix.sync.aligned.m8n8.x4.trans.shared.b16 {%0,%1,%2,%3}, [%4];"
                 : "=r"(r[0]), "=r"(r[1]), "=r"(r[2]), "=r"(r[3]) : "r"(addr));
}
static __device__ __forceinline__ void ldsm2t(uint32_t* r, uint32_t addr) {
    asm volatile("ldmatrix.sync.aligned.m8n8.x2.trans.shared.b16 {%0,%1}, [%2];"
                 : "=r"(r[0]), "=r"(r[1]) : "r"(addr));
}
static __device__ __forceinline__ void mma16816(float* d, const uint32_t* a,
                                                uint32_t b0, uint32_t b1) {
    asm volatile(
        "mma.sync.aligned.m16n8k16.row.col.f32.f16.f16.f32 "
        "{%0,%1,%2,%3},{%4,%5,%6,%7},{%8,%9},{%0,%1,%2,%3};"
        : "+f"(d[0]), "+f"(d[1]), "+f"(d[2]), "+f"(d[3])
        : "r"(a[0]), "r"(a[1]), "r"(a[2]), "r"(a[3]), "r"(b0), "r"(b1));
}
static __device__ __forceinline__ void cp16(uint32_t s, const void* g) {
    asm volatile("cp.async.cg.shared.global [%0], [%1], 16;" :: "r"(s), "l"(g));
}
#define CP_COMMIT asm volatile("cp.async.commit_group;")
#define CP_WAIT0  asm volatile("cp.async.wait_group 0;")
#define CP_WAIT1  asm volatile("cp.async.wait_group 1;")

static __device__ __forceinline__ uint32_t pack_h2(__half a, __half b) {
    __half2 t = __halves2half2(a, b);
    return *reinterpret_cast<uint32_t*>(&t);
}
static __device__ __forceinline__ uint32_t cvt_h2(float lo, float hi) {
    uint32_t r;
    asm("cvt.rn.f16x2.f32 %0, %1, %2;" : "=r"(r) : "f"(hi), "f"(lo));
    return r;
}
static __device__ __forceinline__ uint32_t h2exp2(uint32_t x) {
    uint32_t r;
    asm("ex2.approx.f16x2 %0, %1;" : "=r"(r) : "r"(x));
    return r;
}
static __device__ __forceinline__ void split2(float v0, float v1,
                                              uint32_t& hi, uint32_t& lo) {
    __half h0 = __float2half_rn(v0);
    __half h1 = __float2half_rn(v1);
    __half l0 = __float2half_rn(v0 - __half2float(h0));
    __half l1 = __float2half_rn(v1 - __half2float(h1));
    hi = pack_h2(h0, h1);
    lo = pack_h2(l0, l1);
}

// ---------------------------------------------------------------------------
// split fp32 -> fp16 (hi, lo)
// ---------------------------------------------------------------------------
__global__ void __launch_bounds__(256)
split_bf16(const float* __restrict__ src, __half* __restrict__ hi,
           __half* __restrict__ lo, int n2)
{
    int i = blockIdx.x * 256 + threadIdx.x;
    if (i >= n2) return;
    float2 v = ((const float2*)src)[i];
    uint32_t h, l;
    split2(v.x, v.y, h, l);
    ((uint32_t*)hi)[i] = h;
    ((uint32_t*)lo)[i] = l;
}

__global__ void __launch_bounds__(256)
split4_bf16(const float* __restrict__ s0, const float* __restrict__ s1,
            const float* __restrict__ s2, const float* __restrict__ s3,
            __half* __restrict__ hi, __half* __restrict__ lo, int n2)
{
    int i = blockIdx.x * 256 + threadIdx.x;
    if (i >= n2) return;
    const int y = blockIdx.y;
    const float* s = (y == 0) ? s0 : (y == 1) ? s1 : (y == 2) ? s2 : s3;
    float2 v = ((const float2*)s)[i];
    uint32_t h, l;
    split2(v.x, v.y, h, l);
    const size_t base = (size_t)y * (DM * DM / 2);
    ((uint32_t*)hi)[base + i] = h;
    ((uint32_t*)lo)[base + i] = l;
}

// ---------------------------------------------------------------------------
// mma.sync fp16 GEMM. 128x128x32 tiles, cp.async double-buffered,
// 8 warps (2m x 4n), 2 CTAs/SM. Q output (z==0) pre-scaled by 0.125*log2(e).
// Q,K: 3-term. V & Wo: 2-term. mma issued term-major (same-acc distance 8).
// ---------------------------------------------------------------------------
__global__ void __launch_bounds__(256, 2)
gemm_mma(const __half* __restrict__ Ah_g, const __half* __restrict__ Al_g,
         const __half* __restrict__ WhAll, const __half* __restrict__ WlAll,
         float* __restrict__ C,
         __half* __restrict__ C0h, __half* __restrict__ C0l,
         __half* __restrict__ C1h, __half* __restrict__ C1l,
         __half* __restrict__ C2h, __half* __restrict__ C2l,
         int qkv)
{
    constexpr int K = DM;
    constexpr int TILE  = 10240;   // 128 rows x 40 fp16 (pitch 80B)
    constexpr int STAGE = 4 * TILE;
    extern __shared__ __align__(128) char smg[];
    const uint32_t sbase = s2u(smg);

    const int z   = blockIdx.z;
    const int mode = qkv ? ((z == 2) ? 1 : 2) : 0;
    const bool useBl = qkv && (z < 2);     // 3-term only for Q,K
    const float oscale = (qkv && z == 0) ? 0.125f * 1.44269504f : 1.0f;
    const size_t wsel = qkv ? (size_t)z * DM * DM : (size_t)3 * DM * DM;
    const __half* Bh_g = WhAll + wsel;
    const __half* Bl_g = WlAll + wsel;
    __half* Ch = (z == 0) ? C0h : (z == 1) ? C1h : C2h;
    __half* Cl = (z == 0) ? C0l : (z == 1) ? C1l : C2l;

    const int bm  = blockIdx.y * 128;
    const int bn  = blockIdx.x * 128;
    const int tid = threadIdx.x;
    const int lane = tid & 31;
    const int wid  = tid >> 5;
    const int wm = (wid >> 2) * 64;
    const int wn = (wid & 3) * 32;

    const __half* srcs[4] = {
        Ah_g + (size_t)bm * K, Al_g + (size_t)bm * K,
        Bh_g + (size_t)bn * K, Bl_g + (size_t)bn * K };

    const int ntile = useBl ? 4 : 3;
    auto fill = [&](int s, int kc) {
#pragma unroll
        for (int t = 0; t < 4; ++t) {
            if (t >= ntile) break;
#pragma unroll
            for (int i = 0; i < 2; ++i) {
                const int idx = i * 256 + tid;
                const int r = idx >> 2;
                const int c = idx & 3;
                cp16(sbase + s * STAGE + t * TILE + r * 80 + c * 16,
                     srcs[t] + (size_t)r * K + kc * 32 + c * 8);
            }
        }
        CP_COMMIT;
    };

    float acc[4][4][4] = {};

    fill(0, 0);
    for (int kc = 0; kc < K / 32; ++kc) {
        CP_WAIT0;
        __syncthreads();
        if (kc + 1 < K / 32) fill((kc + 1) & 1, kc + 1);

        const uint32_t aB = sbase + (kc & 1) * STAGE;
        const uint32_t bB = aB + 2 * TILE;
#pragma unroll
        for (int ks = 0; ks < 2; ++ks) {
            uint32_t ah[4][4], al[4][4];
#pragma unroll
            for (int mt = 0; mt < 4; ++mt) {
                const uint32_t ad = aB +
                    ((wm + mt * 16 + (lane & 15)) * 40 + ks * 16 + (lane >> 4) * 8) * 2;
                ldsm4(ah[mt], ad);
                ldsm4(al[mt], ad + TILE);
            }
#pragma unroll
            for (int np = 0; np < 2; ++np) {
                uint32_t bh[4], bl[4];
                const uint32_t ad = bB +
                    ((wn + np * 16 + (lane & 15)) * 40 + ks * 16 + (lane >> 4) * 8) * 2;
                ldsm4(bh, ad);
                if (useBl) ldsm4(bl, ad + TILE);
                // term-major: same-accumulator distance 8
#pragma unroll
                for (int mt = 0; mt < 4; ++mt)
#pragma unroll
                    for (int hf = 0; hf < 2; ++hf)
                        mma16816(acc[mt][np * 2 + hf], ah[mt], bh[hf], bh[hf + 2]);
                if (useBl) {
#pragma unroll
                    for (int mt = 0; mt < 4; ++mt)
#pragma unroll
                        for (int hf = 0; hf < 2; ++hf)
                            mma16816(acc[mt][np * 2 + hf], ah[mt], bl[hf], bl[hf + 2]);
                }
#pragma unroll
                for (int mt = 0; mt < 4; ++mt)
#pragma unroll
                    for (int hf = 0; hf < 2; ++hf)
                        mma16816(acc[mt][np * 2 + hf], al[mt], bh[hf], bh[hf + 2]);
            }
        }
        __syncthreads();
    }

#pragma unroll
    for (int mt = 0; mt < 4; ++mt)
#pragma unroll
        for (int ri = 0; ri < 2; ++ri) {
            const int m = bm + wm + mt * 16 + ri * 8 + (lane >> 2);
#pragma unroll
            for (int nt = 0; nt < 4; ++nt) {
                const int n = bn + wn + nt * 8 + 2 * (lane & 3);
                float v0 = acc[mt][nt][ri * 2 + 0];
                float v1 = acc[mt][nt][ri * 2 + 1];
                if (mode == 0) {
                    *(float2*)(C + (size_t)m * DM + n) = make_float2(v0, v1);
                } else {
                    if (mode == 2) {
                        const int d = n & 63;   // even
                        const float inv = exp2f((float)d * -0.20762050f);
                        float sn, cs;
                        sincosf((float)m * inv, &sn, &cs);
                        const float a = v0, b = v1;
                        v0 = (a * cs - b * sn) * oscale;
                        v1 = (b * cs + a * sn) * oscale;
                    }
                    const int hh = n >> 6;
                    const int d0 = n & 63;
                    const size_t off = ((size_t)hh * SEQ + m) * DK + d0;
                    uint32_t h, l;
                    split2(v0, v1, h, l);
                    *(uint32_t*)(Ch + off) = h;
                    *(uint32_t*)(Cl + off) = l;
                }
            }
        }
}

// ---------------------------------------------------------------------------
// FA2-style flash attention, causal, fp16 mma.
// Br=128 (8 warps x 16 rows), Bc=64, 2 CTAs/SM. Q pre-scaled by 0.125*log2e.
// S 3-term, ng-pair interleaved (same-acc mma distance 4). P via
// ex2.approx.f16x2. l accumulated via ones-column V tile in the tensor core.
// Causal mask hoisted to last 2 iterations.
// ---------------------------------------------------------------------------
#define F_K0  0        // 64x144B hi + lo(+9216)
#define F_K1  18432
#define F_V0  36864    // hi only; bytes 128..143 of each row = ones-column pad
#define F_V1  46080
#define F_Q   55296    // 128x144B hi + lo(+18432)
#define F_TOT 92160

__global__ void __launch_bounds__(256, 2)
flash_tc(const __half* __restrict__ qh, const __half* __restrict__ ql,
         const __half* __restrict__ kh, const __half* __restrict__ kl,
         const __half* __restrict__ vh,
         __half* __restrict__ aoh, __half* __restrict__ aol)
{
    extern __shared__ __align__(128) char sma[];
    const uint32_t sbase = s2u(sma);

    const int h    = blockIdx.y;
    const int qb   = gridDim.x - 1 - blockIdx.x;   // heavy tiles first
    const int tid  = threadIdx.x;
    const int lane = tid & 31;
    const int wid  = tid >> 5;
    const int wm   = wid * 16;
    const int g    = lane >> 2;
    const int tq   = lane & 3;

    const size_t hb = (size_t)h * SEQ * DK;
    const int nkb = 2 * qb + 2;     // number of 64-token blocks

    // ---- prologue: Q (group), K0+V0 (group) ----
    {
        const __half* qgh = qh + hb + (size_t)qb * 128 * DK;
        const __half* qgl = ql + hb + (size_t)qb * 128 * DK;
#pragma unroll
        for (int i = 0; i < 4; ++i) {
            const int idx = i * 256 + tid;
            const int r = idx >> 3;
            const int c = idx & 7;
            cp16(sbase + F_Q + r * 144 + c * 16, qgh + r * 64 + c * 8);
            cp16(sbase + F_Q + 18432 + r * 144 + c * 16, qgl + r * 64 + c * 8);
        }
        CP_COMMIT;
        const __half* kgh = kh + hb;
        const __half* kgl = kl + hb;
        const __half* vgh = vh + hb;
#pragma unroll
        for (int i = 0; i < 2; ++i) {
            const int idx = i * 256 + tid;
            const int r = idx >> 3;        // 0..63
            const int c = idx & 7;
            cp16(sbase + F_K0 + r * 144 + c * 16, kgh + r * 64 + c * 8);
            cp16(sbase + F_K0 + 9216 + r * 144 + c * 16, kgl + r * 64 + c * 8);
            cp16(sbase + F_V0 + r * 144 + c * 16, vgh + r * 64 + c * 8);
        }
        CP_COMMIT;
    }
    // ones-column pad for both V buffers (cp.async never touches bytes 128..143)
    if (tid < 128) {
        const int buf = tid >> 6;
        const int r = tid & 63;
        uint4* p = (uint4*)(sma + (buf ? F_V1 : F_V0) + r * 144 + 128);
        *p = make_uint4(0x00003c00u, 0u, 0u, 0u);
    }
    CP_WAIT1;
    __syncthreads();

    // ---- Q fragments (resident all kernel) ----
    uint32_t qfh[4][4], qfl[4][4];
#pragma unroll
    for (int d16 = 0; d16 < 4; ++d16) {
        const uint32_t ad = sbase + F_Q +
            ((wm + (lane & 15)) * 72 + d16 * 16 + (lane >> 4) * 8) * 2;
        ldsm4(qfh[d16], ad);
        ldsm4(qfl[d16], ad + 18432);
    }

    float oacc[8][4] = {};
    float oaccL[4] = {};            // ones-column accumulator: col0 = sum(p)
    float mrow[2] = { -1e30f, -1e30f };

    auto body = [&](int kb, bool domask) {
        __syncthreads();

        // prefetch K,V (kb+1)
        if (kb + 1 < nkb) {
            const __half* kgh = kh + hb + (size_t)(kb + 1) * 64 * DK;
            const __half* kgl = kl + hb + (size_t)(kb + 1) * 64 * DK;
            const __half* vgh = vh + hb + (size_t)(kb + 1) * 64 * DK;
            const uint32_t kB = sbase + (((kb + 1) & 1) ? F_K1 : F_K0);
            const uint32_t vB = sbase + (((kb + 1) & 1) ? F_V1 : F_V0);
#pragma unroll
            for (int i = 0; i < 2; ++i) {
                const int idx = i * 256 + tid;
                const int r = idx >> 3;
                const int c = idx & 7;
                cp16(kB + r * 144 + c * 16, kgh + r * 64 + c * 8);
                cp16(kB + 9216 + r * 144 + c * 16, kgl + r * 64 + c * 8);
                cp16(vB + r * 144 + c * 16, vgh + r * 64 + c * 8);
            }
        }
        CP_COMMIT;
        CP_WAIT1;
        __syncthreads();

        const uint32_t kBuf = sbase + ((kb & 1) ? F_K1 : F_K0);
        const uint32_t vBuf = sbase + ((kb & 1) ? F_V1 : F_V0);

        // ---- S = Q K^T (3-term); ng pairs, same-acc distance 4 ----
        float sacc[8][4] = {};
#pragma unroll
        for (int d16 = 0; d16 < 4; ++d16) {
#pragma unroll
            for (int ngp = 0; ngp < 2; ++ngp) {
                uint32_t bh0[4], bl0[4], bh1[4], bl1[4];
                const uint32_t ad0 = kBuf +
                    ((ngp * 32 + (lane & 15)) * 72 + d16 * 16 + (lane >> 4) * 8) * 2;
                const uint32_t ad1 = ad0 + 16 * 72 * 2;
                ldsm4(bh0, ad0);
                ldsm4(bl0, ad0 + 9216);
                ldsm4(bh1, ad1);
                ldsm4(bl1, ad1 + 9216);
                float* s0 = sacc[4 * ngp + 0];
                float* s1 = sacc[4 * ngp + 1];
                float* s2 = sacc[4 * ngp + 2];
                float* s3 = sacc[4 * ngp + 3];
                mma16816(s0, qfh[d16], bh0[0], bh0[2]);
                mma16816(s1, qfh[d16], bh0[1], bh0[3]);
                mma16816(s2, qfh[d16], bh1[0], bh1[2]);
                mma16816(s3, qfh[d16], bh1[1], bh1[3]);
                mma16816(s0, qfh[d16], bl0[0], bl0[2]);
                mma16816(s1, qfh[d16], bl0[1], bl0[3]);
                mma16816(s2, qfh[d16], bl1[0], bl1[2]);
                mma16816(s3, qfh[d16], bl1[1], bl1[3]);
                mma16816(s0, qfl[d16], bh0[0], bh0[2]);
                mma16816(s1, qfl[d16], bh0[1], bh0[3]);
                mma16816(s2, qfl[d16], bh1[0], bh1[2]);
                mma16816(s3, qfl[d16], bh1[1], bh1[3]);
            }
        }

        // ---- warp-local online softmax (log2 domain), P -> half2 regs ----
        const int moff = (kb - 2 * qb) * 64;    // used only when domask
        uint32_t ph2[8][2];
        float corr[2];
#pragma unroll
        for (int hf = 0; hf < 2; ++hf) {
            const int rloc = wm + g + hf * 8;
            float vmax = -1e30f;
#pragma unroll
            for (int j = 0; j < 8; ++j)
#pragma unroll
                for (int ci = 0; ci < 2; ++ci) {
                    float v = sacc[j][hf * 2 + ci];
                    if (domask && (moff + 8 * j + 2 * tq + ci) > rloc) {
                        v = -1e30f;
                        sacc[j][hf * 2 + ci] = v;
                    }
                    vmax = fmaxf(vmax, v);
                }
            vmax = fmaxf(vmax, __shfl_xor_sync(0xffffffffu, vmax, 1));
            vmax = fmaxf(vmax, __shfl_xor_sync(0xffffffffu, vmax, 2));
            const float mnew = fmaxf(mrow[hf], vmax);
            corr[hf] = exp2f(mrow[hf] - mnew);
            mrow[hf] = mnew;
#pragma unroll
            for (int j = 0; j < 8; ++j)
                ph2[j][hf] = h2exp2(cvt_h2(sacc[j][hf * 2 + 0] - mnew,
                                           sacc[j][hf * 2 + 1] - mnew));
#pragma unroll
            for (int j = 0; j < 8; ++j) {
                oacc[j][hf * 2 + 0] *= corr[hf];
                oacc[j][hf * 2 + 1] *= corr[hf];
            }
            oaccL[hf * 2 + 0] *= corr[hf];
            oaccL[hf * 2 + 1] *= corr[hf];
        }

        // ---- O += P V ; l += P·1 (ones column) ----
#pragma unroll
        for (int kt = 0; kt < 4; ++kt) {
            uint32_t ah[4];
            ah[0] = ph2[2 * kt][0];
            ah[1] = ph2[2 * kt][1];
            ah[2] = ph2[2 * kt + 1][0];
            ah[3] = ph2[2 * kt + 1][1];
            const int t_loc = kt * 16 + (lane & 7) + ((lane >> 3) & 1) * 8;
#pragma unroll
            for (int ng = 0; ng < 4; ++ng) {
                uint32_t bh[4];
                const int d_loc = ng * 16 + ((lane >> 4) & 1) * 8;
                const uint32_t ad = vBuf + (uint32_t)(t_loc * 72 + d_loc) * 2;
                ldsm4t(bh, ad);
                mma16816(oacc[2 * ng],     ah, bh[0], bh[1]);
                mma16816(oacc[2 * ng + 1], ah, bh[2], bh[3]);
            }
            {
                uint32_t bo[2];
                ldsm2t(bo, vBuf + (uint32_t)(t_loc * 72 + 64) * 2);
                mma16816(oaccL, ah, bo[0], bo[1]);
            }
        }
    };

    for (int kb = 0; kb < nkb - 2; ++kb) body(kb, false);
    body(nkb - 2, true);
    body(nkb - 1, true);

    // ---- epilogue: l from ones-column (col 0 -> tq==0), broadcast in quad ----
#pragma unroll
    for (int hf = 0; hf < 2; ++hf) {
        const float lv = __shfl_sync(0xffffffffu, oaccL[hf * 2 + 0], lane & ~3);
        const float inv = 1.f / lv;
        const int q = qb * 128 + wm + g + hf * 8;
#pragma unroll
        for (int j = 0; j < 8; ++j) {
            const float v0 = oacc[j][hf * 2 + 0] * inv;
            const float v1 = oacc[j][hf * 2 + 1] * inv;
            const int col = h * 64 + 8 * j + 2 * tq;
            uint32_t hw, lw;
            split2(v0, v1, hw, lw);
            *(uint32_t*)(aoh + (size_t)q * DM + col) = hw;
            *(uint32_t*)(aol + (size_t)q * DM + col) = lw;
        }
    }
}

// ---------------------------------------------------------------------------
extern "C" void kernel_launch(void* const* d_in, const int* in_sizes, int n_in,
                              void* d_out, int out_size)
{
    const float* x  = (const float*)d_in[0];
    const float* Wq = (const float*)d_in[1];
    const float* Wk = (const float*)d_in[2];
    const float* Wv = (const float*)d_in[3];
    const float* Wo = (const float*)d_in[4];

    __half *xh, *xl, *wh, *wl, *qhp, *qlp, *khp, *klp, *vhp, *aoh, *aol;
    cudaGetSymbolAddress((void**)&xh,  g_xh);
    cudaGetSymbolAddress((void**)&xl,  g_xl);
    cudaGetSymbolAddress((void**)&wh,  g_wh);
    cudaGetSymbolAddress((void**)&wl,  g_wl);
    cudaGetSymbolAddress((void**)&qhp, g_qh);
    cudaGetSymbolAddress((void**)&qlp, g_ql);
    cudaGetSymbolAddress((void**)&khp, g_kh);
    cudaGetSymbolAddress((void**)&klp, g_kl);
    cudaGetSymbolAddress((void**)&vhp, g_vh);
    cudaGetSymbolAddress((void**)&aoh, g_aoh);
    cudaGetSymbolAddress((void**)&aol, g_aol);

    const int nx2 = SEQ * DM / 2;
    const int nw2 = DM * DM / 2;
    split_bf16<<<(nx2 + 255) / 256, 256>>>(x, xh, xl, nx2);
    split4_bf16<<<dim3((nw2 + 255) / 256, 4), 256>>>(Wq, Wk, Wv, Wo, wh, wl, nw2);

    const int gsm = 2 * 4 * 10240;   // 81,920 B
    cudaFuncSetAttribute(gemm_mma, cudaFuncAttributeMaxDynamicSharedMemorySize, gsm);
    cudaFuncSetAttribute(flash_tc, cudaFuncAttributeMaxDynamicSharedMemorySize, F_TOT);

    // fused Q/K/V projections (Q pre-scaled by 0.125*log2e); V lo -> dummy
    // target aol, fully overwritten by flash epilogue afterwards.
    gemm_mma<<<dim3(DM / 128, SEQ / 128, 3), 256, gsm>>>(
        xh, xl, wh, wl, nullptr, qhp, qlp, khp, klp, vhp, aol, 1);

    flash_tc<<<dim3(SEQ / 128, NH), 256, F_TOT>>>(qhp, qlp, khp, klp, vhp, aoh, aol);

    // Wo projection (2-term, weights hi only)
    gemm_mma<<<dim3(DM / 128, SEQ / 128, 1), 256, gsm>>>(
        aoh, aol, wh, wl, (float*)d_out,
        nullptr, nullptr, nullptr, nullptr, nullptr, nullptr, 0);
}

// round 13
// speedup vs baseline: 1.1479x; 1.1479x over previous
#include <cuda_runtime.h>
#include <cuda_fp16.h>
#include <math.h>
#include <stdint.h>

#define SEQ 4096
#define DM  1024
#define NH  16
#define DK  64

// ---------------------------------------------------------------------------
// scratch (no allocs allowed) — fp16 hi/lo pairs (K,V consumed hi-only)
// ---------------------------------------------------------------------------
__device__ __half g_xh [SEQ * DM];
__device__ __half g_xl [SEQ * DM];
__device__ __half g_wh [4][DM * DM];
__device__ __half g_wl [4][DM * DM];
__device__ __half g_qh [NH * SEQ * DK];
__device__ __half g_ql [NH * SEQ * DK];
__device__ __half g_kh [NH * SEQ * DK];
__device__ __half g_kl [NH * SEQ * DK];
__device__ __half g_vh [NH * SEQ * DK];
__device__ __half g_aoh[SEQ * DM];
__device__ __half g_aol[SEQ * DM];

// ---------------------------------------------------------------------------
// helpers
// ---------------------------------------------------------------------------
static __device__ __forceinline__ uint32_t s2u(const void* p) {
    uint32_t a;
    asm("{ .reg .u64 t; cvta.to.shared.u64 t, %1; cvt.u32.u64 %0, t; }"
        : "=r"(a) : "l"(p));
    return a;
}
static __device__ __forceinline__ void ldsm4(uint32_t* r, uint32_t addr) {
    asm volatile("ldmatrix.sync.aligned.m8n8.x4.shared.b16 {%0,%1,%2,%3}, [%4];"
                 : "=r"(r[0]), "=r"(r[1]), "=r"(r[2]), "=r"(r[3]) : "r"(addr));
}
static __device__ __forceinline__ void ldsm4t(uint32_t* r, uint32_t addr) {
    asm volatile("ldmatrix.sync.aligned.m8n8.x4.trans.shared.b16 {%0,%1,%2,%3}, [%4];"
                 : "=r"(r[0]), "=r"(r[1]), "=r"(r[2]), "=r"(r[3]) : "r"(addr));
}
static __device__ __forceinline__ void ldsm2t(uint32_t* r, uint32_t addr) {
    asm volatile("ldmatrix.sync.aligned.m8n8.x2.trans.shared.b16 {%0,%1}, [%2];"
                 : "=r"(r[0]), "=r"(r[1]) : "r"(addr));
}
static __device__ __forceinline__ void mma16816(float* d, const uint32_t* a,
                                                uint32_t b0, uint32_t b1) {
    asm volatile(
        "mma.sync.aligned.m16n8k16.row.col.f32.f16.f16.f32 "
        "{%0,%1,%2,%3},{%4,%5,%6,%7},{%8,%9},{%0,%1,%2,%3};"
        : "+f"(d[0]), "+f"(d[1]), "+f"(d[2]), "+f"(d[3])
        : "r"(a[0]), "r"(a[1]), "r"(a[2]), "r"(a[3]), "r"(b0), "r"(b1));
}
static __device__ __forceinline__ void cp16(uint32_t s, const void* g) {
    asm volatile("cp.async.cg.shared.global [%0], [%1], 16;" :: "r"(s), "l"(g));
}
#define CP_COMMIT asm volatile("cp.async.commit_group;")
#define CP_WAIT0  asm volatile("cp.async.wait_group 0;")
#define CP_WAIT1  asm volatile("cp.async.wait_group 1;")

static __device__ __forceinline__ uint32_t pack_h2(__half a, __half b) {
    __half2 t = __halves2half2(a, b);
    return *reinterpret_cast<uint32_t*>(&t);
}
static __device__ __forceinline__ uint32_t cvt_h2(float lo, float hi) {
    uint32_t r;
    asm("cvt.rn.f16x2.f32 %0, %1, %2;" : "=r"(r) : "f"(hi), "f"(lo));
    return r;
}
static __device__ __forceinline__ uint32_t h2exp2(uint32_t x) {
    uint32_t r;
    asm("ex2.approx.f16x2 %0, %1;" : "=r"(r) : "r"(x));
    return r;
}
static __device__ __forceinline__ void split2(float v0, float v1,
                                              uint32_t& hi, uint32_t& lo) {
    __half h0 = __float2half_rn(v0);
    __half h1 = __float2half_rn(v1);
    __half l0 = __float2half_rn(v0 - __half2float(h0));
    __half l1 = __float2half_rn(v1 - __half2float(h1));
    hi = pack_h2(h0, h1);
    lo = pack_h2(l0, l1);
}

// ---------------------------------------------------------------------------
// split fp32 -> fp16 (hi, lo)
// ---------------------------------------------------------------------------
__global__ void __launch_bounds__(256)
split_bf16(const float* __restrict__ src, __half* __restrict__ hi,
           __half* __restrict__ lo, int n2)
{
    int i = blockIdx.x * 256 + threadIdx.x;
    if (i >= n2) return;
    float2 v = ((const float2*)src)[i];
    uint32_t h, l;
    split2(v.x, v.y, h, l);
    ((uint32_t*)hi)[i] = h;
    ((uint32_t*)lo)[i] = l;
}

__global__ void __launch_bounds__(256)
split4_bf16(const float* __restrict__ s0, const float* __restrict__ s1,
            const float* __restrict__ s2, const float* __restrict__ s3,
            __half* __restrict__ hi, __half* __restrict__ lo, int n2)
{
    int i = blockIdx.x * 256 + threadIdx.x;
    if (i >= n2) return;
    const int y = blockIdx.y;
    const float* s = (y == 0) ? s0 : (y == 1) ? s1 : (y == 2) ? s2 : s3;
    float2 v = ((const float2*)s)[i];
    uint32_t h, l;
    split2(v.x, v.y, h, l);
    const size_t base = (size_t)y * (DM * DM / 2);
    ((uint32_t*)hi)[base + i] = h;
    ((uint32_t*)lo)[base + i] = l;
}

// ---------------------------------------------------------------------------
// mma.sync fp16 GEMM. 128x128x32 tiles, cp.async double-buffered,
// 8 warps (2m x 4n), 2 CTAs/SM. Q output (z==0) pre-scaled by 0.125*log2(e).
// Q,K: 3-term. V & Wo: 2-term. mma issued term-major (same-acc distance 8).
// ---------------------------------------------------------------------------
__global__ void __launch_bounds__(256, 2)
gemm_mma(const __half* __restrict__ Ah_g, const __half* __restrict__ Al_g,
         const __half* __restrict__ WhAll, const __half* __restrict__ WlAll,
         float* __restrict__ C,
         __half* __restrict__ C0h, __half* __restrict__ C0l,
         __half* __restrict__ C1h, __half* __restrict__ C1l,
         __half* __restrict__ C2h, __half* __restrict__ C2l,
         int qkv)
{
    constexpr int K = DM;
    constexpr int TILE  = 10240;   // 128 rows x 40 fp16 (pitch 80B)
    constexpr int STAGE = 4 * TILE;
    extern __shared__ __align__(128) char smg[];
    const uint32_t sbase = s2u(smg);

    const int z   = blockIdx.z;
    const int mode = qkv ? ((z == 2) ? 1 : 2) : 0;
    const bool useBl = qkv && (z < 2);     // 3-term only for Q,K
    const float oscale = (qkv && z == 0) ? 0.125f * 1.44269504f : 1.0f;
    const size_t wsel = qkv ? (size_t)z * DM * DM : (size_t)3 * DM * DM;
    const __half* Bh_g = WhAll + wsel;
    const __half* Bl_g = WlAll + wsel;
    __half* Ch = (z == 0) ? C0h : (z == 1) ? C1h : C2h;
    __half* Cl = (z == 0) ? C0l : (z == 1) ? C1l : C2l;

    const int bm  = blockIdx.y * 128;
    const int bn  = blockIdx.x * 128;
    const int tid = threadIdx.x;
    const int lane = tid & 31;
    const int wid  = tid >> 5;
    const int wm = (wid >> 2) * 64;
    const int wn = (wid & 3) * 32;

    const __half* srcs[4] = {
        Ah_g + (size_t)bm * K, Al_g + (size_t)bm * K,
        Bh_g + (size_t)bn * K, Bl_g + (size_t)bn * K };

    const int ntile = useBl ? 4 : 3;
    auto fill = [&](int s, int kc) {
#pragma unroll
        for (int t = 0; t < 4; ++t) {
            if (t >= ntile) break;
#pragma unroll
            for (int i = 0; i < 2; ++i) {
                const int idx = i * 256 + tid;
                const int r = idx >> 2;
                const int c = idx & 3;
                cp16(sbase + s * STAGE + t * TILE + r * 80 + c * 16,
                     srcs[t] + (size_t)r * K + kc * 32 + c * 8);
            }
        }
        CP_COMMIT;
    };

    float acc[4][4][4] = {};

    fill(0, 0);
    for (int kc = 0; kc < K / 32; ++kc) {
        CP_WAIT0;
        __syncthreads();
        if (kc + 1 < K / 32) fill((kc + 1) & 1, kc + 1);

        const uint32_t aB = sbase + (kc & 1) * STAGE;
        const uint32_t bB = aB + 2 * TILE;
#pragma unroll
        for (int ks = 0; ks < 2; ++ks) {
            uint32_t ah[4][4], al[4][4];
#pragma unroll
            for (int mt = 0; mt < 4; ++mt) {
                const uint32_t ad = aB +
                    ((wm + mt * 16 + (lane & 15)) * 40 + ks * 16 + (lane >> 4) * 8) * 2;
                ldsm4(ah[mt], ad);
                ldsm4(al[mt], ad + TILE);
            }
#pragma unroll
            for (int np = 0; np < 2; ++np) {
                uint32_t bh[4], bl[4];
                const uint32_t ad = bB +
                    ((wn + np * 16 + (lane & 15)) * 40 + ks * 16 + (lane >> 4) * 8) * 2;
                ldsm4(bh, ad);
                if (useBl) ldsm4(bl, ad + TILE);
#pragma unroll
                for (int mt = 0; mt < 4; ++mt)
#pragma unroll
                    for (int hf = 0; hf < 2; ++hf)
                        mma16816(acc[mt][np * 2 + hf], ah[mt], bh[hf], bh[hf + 2]);
                if (useBl) {
#pragma unroll
                    for (int mt = 0; mt < 4; ++mt)
#pragma unroll
                        for (int hf = 0; hf < 2; ++hf)
                            mma16816(acc[mt][np * 2 + hf], ah[mt], bl[hf], bl[hf + 2]);
                }
#pragma unroll
                for (int mt = 0; mt < 4; ++mt)
#pragma unroll
                    for (int hf = 0; hf < 2; ++hf)
                        mma16816(acc[mt][np * 2 + hf], al[mt], bh[hf], bh[hf + 2]);
            }
        }
        __syncthreads();
    }

#pragma unroll
    for (int mt = 0; mt < 4; ++mt)
#pragma unroll
        for (int ri = 0; ri < 2; ++ri) {
            const int m = bm + wm + mt * 16 + ri * 8 + (lane >> 2);
#pragma unroll
            for (int nt = 0; nt < 4; ++nt) {
                const int n = bn + wn + nt * 8 + 2 * (lane & 3);
                float v0 = acc[mt][nt][ri * 2 + 0];
                float v1 = acc[mt][nt][ri * 2 + 1];
                if (mode == 0) {
                    *(float2*)(C + (size_t)m * DM + n) = make_float2(v0, v1);
                } else {
                    if (mode == 2) {
                        const int d = n & 63;   // even
                        const float inv = exp2f((float)d * -0.20762050f);
                        float sn, cs;
                        sincosf((float)m * inv, &sn, &cs);
                        const float a = v0, b = v1;
                        v0 = (a * cs - b * sn) * oscale;
                        v1 = (b * cs + a * sn) * oscale;
                    }
                    const int hh = n >> 6;
                    const int d0 = n & 63;
                    const size_t off = ((size_t)hh * SEQ + m) * DK + d0;
                    uint32_t h, l;
                    split2(v0, v1, h, l);
                    *(uint32_t*)(Ch + off) = h;
                    *(uint32_t*)(Cl + off) = l;
                }
            }
        }
}

// ---------------------------------------------------------------------------
// FA2-style flash attention, causal, fp16 mma.
// Br=128 (8 warps x 16 rows), Bc=64, 2 CTAs/SM. Q pre-scaled by 0.125*log2e.
// S = (Qh+Ql)·Kh 2-term (K single fp16 — Kl dropped; error ~1.4e-4).
// P via ex2.approx.f16x2; l via ones-column V tile in the tensor core.
// Causal mask hoisted to last 2 iterations.
// ---------------------------------------------------------------------------
#define F_K0  0        // 64x144B, hi only
#define F_K1  9216
#define F_V0  18432    // hi only; bytes 128..143 of each row = ones-column pad
#define F_V1  27648
#define F_Q   36864    // 128x144B hi + lo(+18432)
#define F_TOT 73728

__global__ void __launch_bounds__(256, 2)
flash_tc(const __half* __restrict__ qh, const __half* __restrict__ ql,
         const __half* __restrict__ kh,
         const __half* __restrict__ vh,
         __half* __restrict__ aoh, __half* __restrict__ aol)
{
    extern __shared__ __align__(128) char sma[];
    const uint32_t sbase = s2u(sma);

    const int h    = blockIdx.y;
    const int qb   = gridDim.x - 1 - blockIdx.x;   // heavy tiles first
    const int tid  = threadIdx.x;
    const int lane = tid & 31;
    const int wid  = tid >> 5;
    const int wm   = wid * 16;
    const int g    = lane >> 2;
    const int tq   = lane & 3;

    const size_t hb = (size_t)h * SEQ * DK;
    const int nkb = 2 * qb + 2;     // number of 64-token blocks

    // ---- prologue: Q (group), K0+V0 (group) ----
    {
        const __half* qgh = qh + hb + (size_t)qb * 128 * DK;
        const __half* qgl = ql + hb + (size_t)qb * 128 * DK;
#pragma unroll
        for (int i = 0; i < 4; ++i) {
            const int idx = i * 256 + tid;
            const int r = idx >> 3;
            const int c = idx & 7;
            cp16(sbase + F_Q + r * 144 + c * 16, qgh + r * 64 + c * 8);
            cp16(sbase + F_Q + 18432 + r * 144 + c * 16, qgl + r * 64 + c * 8);
        }
        CP_COMMIT;
        const __half* kgh = kh + hb;
        const __half* vgh = vh + hb;
#pragma unroll
        for (int i = 0; i < 2; ++i) {
            const int idx = i * 256 + tid;
            const int r = idx >> 3;        // 0..63
            const int c = idx & 7;
            cp16(sbase + F_K0 + r * 144 + c * 16, kgh + r * 64 + c * 8);
            cp16(sbase + F_V0 + r * 144 + c * 16, vgh + r * 64 + c * 8);
        }
        CP_COMMIT;
    }
    // ones-column pad for both V buffers (cp.async never touches bytes 128..143)
    if (tid < 128) {
        const int buf = tid >> 6;
        const int r = tid & 63;
        uint4* p = (uint4*)(sma + (buf ? F_V1 : F_V0) + r * 144 + 128);
        *p = make_uint4(0x00003c00u, 0u, 0u, 0u);
    }
    CP_WAIT1;
    __syncthreads();

    // ---- Q fragments (resident all kernel) ----
    uint32_t qfh[4][4], qfl[4][4];
#pragma unroll
    for (int d16 = 0; d16 < 4; ++d16) {
        const uint32_t ad = sbase + F_Q +
            ((wm + (lane & 15)) * 72 + d16 * 16 + (lane >> 4) * 8) * 2;
        ldsm4(qfh[d16], ad);
        ldsm4(qfl[d16], ad + 18432);
    }

    float oacc[8][4] = {};
    float oaccL[4] = {};            // ones-column accumulator: col0 = sum(p)
    float mrow[2] = { -1e30f, -1e30f };

    auto body = [&](int kb, bool domask) {
        __syncthreads();

        // prefetch K,V (kb+1)
        if (kb + 1 < nkb) {
            const __half* kgh = kh + hb + (size_t)(kb + 1) * 64 * DK;
            const __half* vgh = vh + hb + (size_t)(kb + 1) * 64 * DK;
            const uint32_t kB = sbase + (((kb + 1) & 1) ? F_K1 : F_K0);
            const uint32_t vB = sbase + (((kb + 1) & 1) ? F_V1 : F_V0);
#pragma unroll
            for (int i = 0; i < 2; ++i) {
                const int idx = i * 256 + tid;
                const int r = idx >> 3;
                const int c = idx & 7;
                cp16(kB + r * 144 + c * 16, kgh + r * 64 + c * 8);
                cp16(vB + r * 144 + c * 16, vgh + r * 64 + c * 8);
            }
        }
        CP_COMMIT;
        CP_WAIT1;
        __syncthreads();

        const uint32_t kBuf = sbase + ((kb & 1) ? F_K1 : F_K0);
        const uint32_t vBuf = sbase + ((kb & 1) ? F_V1 : F_V0);

        // ---- S = (Qh + Ql) · Kh (2-term) ----
        float sacc[8][4] = {};
#pragma unroll
        for (int d16 = 0; d16 < 4; ++d16) {
#pragma unroll
            for (int ng = 0; ng < 4; ++ng) {
                uint32_t bh[4];
                const uint32_t ad = kBuf +
                    ((ng * 16 + (lane & 15)) * 72 + d16 * 16 + (lane >> 4) * 8) * 2;
                ldsm4(bh, ad);
                mma16816(sacc[2 * ng],     qfh[d16], bh[0], bh[2]);
                mma16816(sacc[2 * ng + 1], qfh[d16], bh[1], bh[3]);
                mma16816(sacc[2 * ng],     qfl[d16], bh[0], bh[2]);
                mma16816(sacc[2 * ng + 1], qfl[d16], bh[1], bh[3]);
            }
        }

        // ---- warp-local online softmax (log2 domain), P -> half2 regs ----
        const int moff = (kb - 2 * qb) * 64;    // used only when domask
        uint32_t ph2[8][2];
        float corr[2];
#pragma unroll
        for (int hf = 0; hf < 2; ++hf) {
            const int rloc = wm + g + hf * 8;
            float vmax = -1e30f;
#pragma unroll
            for (int j = 0; j < 8; ++j)
#pragma unroll
                for (int ci = 0; ci < 2; ++ci) {
                    float v = sacc[j][hf * 2 + ci];
                    if (domask && (moff + 8 * j + 2 * tq + ci) > rloc) {
                        v = -1e30f;
                        sacc[j][hf * 2 + ci] = v;
                    }
                    vmax = fmaxf(vmax, v);
                }
            vmax = fmaxf(vmax, __shfl_xor_sync(0xffffffffu, vmax, 1));
            vmax = fmaxf(vmax, __shfl_xor_sync(0xffffffffu, vmax, 2));
            const float mnew = fmaxf(mrow[hf], vmax);
            corr[hf] = exp2f(mrow[hf] - mnew);
            mrow[hf] = mnew;
#pragma unroll
            for (int j = 0; j < 8; ++j)
                ph2[j][hf] = h2exp2(cvt_h2(sacc[j][hf * 2 + 0] - mnew,
                                           sacc[j][hf * 2 + 1] - mnew));
#pragma unroll
            for (int j = 0; j < 8; ++j) {
                oacc[j][hf * 2 + 0] *= corr[hf];
                oacc[j][hf * 2 + 1] *= corr[hf];
            }
            oaccL[hf * 2 + 0] *= corr[hf];
            oaccL[hf * 2 + 1] *= corr[hf];
        }

        // ---- O += P V ; l += P·1 (ones column) ----
#pragma unroll
        for (int kt = 0; kt < 4; ++kt) {
            uint32_t ah[4];
            ah[0] = ph2[2 * kt][0];
            ah[1] = ph2[2 * kt][1];
            ah[2] = ph2[2 * kt + 1][0];
            ah[3] = ph2[2 * kt + 1][1];
            const int t_loc = kt * 16 + (lane & 7) + ((lane >> 3) & 1) * 8;
#pragma unroll
            for (int ng = 0; ng < 4; ++ng) {
                uint32_t bh[4];
                const int d_loc = ng * 16 + ((lane >> 4) & 1) * 8;
                const uint32_t ad = vBuf + (uint32_t)(t_loc * 72 + d_loc) * 2;
                ldsm4t(bh, ad);
                mma16816(oacc[2 * ng],     ah, bh[0], bh[1]);
                mma16816(oacc[2 * ng + 1], ah, bh[2], bh[3]);
            }
            {
                uint32_t bo[2];
                ldsm2t(bo, vBuf + (uint32_t)(t_loc * 72 + 64) * 2);
                mma16816(oaccL, ah, bo[0], bo[1]);
            }
        }
    };

    for (int kb = 0; kb < nkb - 2; ++kb) body(kb, false);
    body(nkb - 2, true);
    body(nkb - 1, true);

    // ---- epilogue: l from ones-column (col 0 -> tq==0), broadcast in quad ----
#pragma unroll
    for (int hf = 0; hf < 2; ++hf) {
        const float lv = __shfl_sync(0xffffffffu, oaccL[hf * 2 + 0], lane & ~3);
        const float inv = 1.f / lv;
        const int q = qb * 128 + wm + g + hf * 8;
#pragma unroll
        for (int j = 0; j < 8; ++j) {
            const float v0 = oacc[j][hf * 2 + 0] * inv;
            const float v1 = oacc[j][hf * 2 + 1] * inv;
            const int col = h * 64 + 8 * j + 2 * tq;
            uint32_t hw, lw;
            split2(v0, v1, hw, lw);
            *(uint32_t*)(aoh + (size_t)q * DM + col) = hw;
            *(uint32_t*)(aol + (size_t)q * DM + col) = lw;
        }
    }
}

// ---------------------------------------------------------------------------
extern "C" void kernel_launch(void* const* d_in, const int* in_sizes, int n_in,
                              void* d_out, int out_size)
{
    const float* x  = (const float*)d_in[0];
    const float* Wq = (const float*)d_in[1];
    const float* Wk = (const float*)d_in[2];
    const float* Wv = (const float*)d_in[3];
    const float* Wo = (const float*)d_in[4];

    __half *xh, *xl, *wh, *wl, *qhp, *qlp, *khp, *klp, *vhp, *aoh, *aol;
    cudaGetSymbolAddress((void**)&xh,  g_xh);
    cudaGetSymbolAddress((void**)&xl,  g_xl);
    cudaGetSymbolAddress((void**)&wh,  g_wh);
    cudaGetSymbolAddress((void**)&wl,  g_wl);
    cudaGetSymbolAddress((void**)&qhp, g_qh);
    cudaGetSymbolAddress((void**)&qlp, g_ql);
    cudaGetSymbolAddress((void**)&khp, g_kh);
    cudaGetSymbolAddress((void**)&klp, g_kl);
    cudaGetSymbolAddress((void**)&vhp, g_vh);
    cudaGetSymbolAddress((void**)&aoh, g_aoh);
    cudaGetSymbolAddress((void**)&aol, g_aol);

    const int nx2 = SEQ * DM / 2;
    const int nw2 = DM * DM / 2;
    split_bf16<<<(nx2 + 255) / 256, 256>>>(x, xh, xl, nx2);
    split4_bf16<<<dim3((nw2 + 255) / 256, 4), 256>>>(Wq, Wk, Wv, Wo, wh, wl, nw2);

    const int gsm = 2 * 4 * 10240;   // 81,920 B
    cudaFuncSetAttribute(gemm_mma, cudaFuncAttributeMaxDynamicSharedMemorySize, gsm);
    cudaFuncSetAttribute(flash_tc, cudaFuncAttributeMaxDynamicSharedMemorySize, F_TOT);

    // fused Q/K/V projections (Q pre-scaled by 0.125*log2e); K lo and V lo are
    // not consumed by flash — klp / aol are dummy targets (aol fully
    // overwritten by the flash epilogue afterwards).
    gemm_mma<<<dim3(DM / 128, SEQ / 128, 3), 256, gsm>>>(
        xh, xl, wh, wl, nullptr, qhp, qlp, khp, klp, vhp, aol, 1);

    flash_tc<<<dim3(SEQ / 128, NH), 256, F_TOT>>>(qhp, qlp, khp, vhp, aoh, aol);

    // Wo projection (2-term, weights hi only)
    gemm_mma<<<dim3(DM / 128, SEQ / 128, 1), 256, gsm>>>(
        aoh, aol, wh, wl, (float*)d_out,
        nullptr, nullptr, nullptr, nullptr, nullptr, nullptr, 0);
}

// round 14
// speedup vs baseline: 1.2518x; 1.0904x over previous
#include <cuda_runtime.h>
#include <cuda_fp16.h>
#include <math.h>
#include <stdint.h>

#define SEQ 4096
#define DM  1024
#define NH  16
#define DK  64

// ---------------------------------------------------------------------------
// scratch (no allocs allowed) — fp16; weights hi-only, x/ao split hi+lo
// ---------------------------------------------------------------------------
__device__ __half g_xh [SEQ * DM];
__device__ __half g_xl [SEQ * DM];
__device__ __half g_wh [4][DM * DM];
__device__ __half g_qh [NH * SEQ * DK];
__device__ __half g_ql [NH * SEQ * DK];
__device__ __half g_kh [NH * SEQ * DK];
__device__ __half g_kl [NH * SEQ * DK];
__device__ __half g_vh [NH * SEQ * DK];
__device__ __half g_aoh[SEQ * DM];
__device__ __half g_aol[SEQ * DM];

// ---------------------------------------------------------------------------
// helpers
// ---------------------------------------------------------------------------
static __device__ __forceinline__ uint32_t s2u(const void* p) {
    uint32_t a;
    asm("{ .reg .u64 t; cvta.to.shared.u64 t, %1; cvt.u32.u64 %0, t; }"
        : "=r"(a) : "l"(p));
    return a;
}
static __device__ __forceinline__ void ldsm4(uint32_t* r, uint32_t addr) {
    asm volatile("ldmatrix.sync.aligned.m8n8.x4.shared.b16 {%0,%1,%2,%3}, [%4];"
                 : "=r"(r[0]), "=r"(r[1]), "=r"(r[2]), "=r"(r[3]) : "r"(addr));
}
static __device__ __forceinline__ void ldsm4t(uint32_t* r, uint32_t addr) {
    asm volatile("ldmatrix.sync.aligned.m8n8.x4.trans.shared.b16 {%0,%1,%2,%3}, [%4];"
                 : "=r"(r[0]), "=r"(r[1]), "=r"(r[2]), "=r"(r[3]) : "r"(addr));
}
static __device__ __forceinline__ void ldsm2t(uint32_t* r, uint32_t addr) {
    asm volatile("ldmatrix.sync.aligned.m8n8.x2.trans.shared.b16 {%0,%1}, [%2];"
                 : "=r"(r[0]), "=r"(r[1]) : "r"(addr));
}
static __device__ __forceinline__ void mma16816(float* d, const uint32_t* a,
                                                uint32_t b0, uint32_t b1) {
    asm volatile(
        "mma.sync.aligned.m16n8k16.row.col.f32.f16.f16.f32 "
        "{%0,%1,%2,%3},{%4,%5,%6,%7},{%8,%9},{%0,%1,%2,%3};"
        : "+f"(d[0]), "+f"(d[1]), "+f"(d[2]), "+f"(d[3])
        : "r"(a[0]), "r"(a[1]), "r"(a[2]), "r"(a[3]), "r"(b0), "r"(b1));
}
static __device__ __forceinline__ void cp16(uint32_t s, const void* g) {
    asm volatile("cp.async.cg.shared.global [%0], [%1], 16;" :: "r"(s), "l"(g));
}
#define CP_COMMIT asm volatile("cp.async.commit_group;")
#define CP_WAIT0  asm volatile("cp.async.wait_group 0;")
#define CP_WAIT1  asm volatile("cp.async.wait_group 1;")

static __device__ __forceinline__ uint32_t pack_h2(__half a, __half b) {
    __half2 t = __halves2half2(a, b);
    return *reinterpret_cast<uint32_t*>(&t);
}
static __device__ __forceinline__ uint32_t cvt_h2(float lo, float hi) {
    uint32_t r;
    asm("cvt.rn.f16x2.f32 %0, %1, %2;" : "=r"(r) : "f"(hi), "f"(lo));
    return r;
}
static __device__ __forceinline__ uint32_t h2exp2(uint32_t x) {
    uint32_t r;
    asm("ex2.approx.f16x2 %0, %1;" : "=r"(r) : "r"(x));
    return r;
}
static __device__ __forceinline__ void split2(float v0, float v1,
                                              uint32_t& hi, uint32_t& lo) {
    __half h0 = __float2half_rn(v0);
    __half h1 = __float2half_rn(v1);
    __half l0 = __float2half_rn(v0 - __half2float(h0));
    __half l1 = __float2half_rn(v1 - __half2float(h1));
    hi = pack_h2(h0, h1);
    lo = pack_h2(l0, l1);
}

// ---------------------------------------------------------------------------
// split fp32 -> fp16 (hi, lo) for x; weights: hi-only convert (4 at once)
// ---------------------------------------------------------------------------
__global__ void __launch_bounds__(256)
split_bf16(const float* __restrict__ src, __half* __restrict__ hi,
           __half* __restrict__ lo, int n2)
{
    int i = blockIdx.x * 256 + threadIdx.x;
    if (i >= n2) return;
    float2 v = ((const float2*)src)[i];
    uint32_t h, l;
    split2(v.x, v.y, h, l);
    ((uint32_t*)hi)[i] = h;
    ((uint32_t*)lo)[i] = l;
}

__global__ void __launch_bounds__(256)
cvt4_f16(const float* __restrict__ s0, const float* __restrict__ s1,
         const float* __restrict__ s2, const float* __restrict__ s3,
         __half* __restrict__ hi, int n2)
{
    int i = blockIdx.x * 256 + threadIdx.x;
    if (i >= n2) return;
    const int y = blockIdx.y;
    const float* s = (y == 0) ? s0 : (y == 1) ? s1 : (y == 2) ? s2 : s3;
    float2 v = ((const float2*)s)[i];
    ((uint32_t*)hi)[(size_t)y * (DM * DM / 2) + i] = cvt_h2(v.x, v.y);
}

// ---------------------------------------------------------------------------
// mma.sync fp16 2-term GEMM: C = (Ah + Al) · Bh^T. 128x128x32 tiles,
// cp.async double-buffered (3 tiles/stage), 8 warps (2m x 4n), 2 CTAs/SM.
// Q output (z==0) pre-scaled by 0.125*log2(e).
// ---------------------------------------------------------------------------
__global__ void __launch_bounds__(256, 2)
gemm_mma(const __half* __restrict__ Ah_g, const __half* __restrict__ Al_g,
         const __half* __restrict__ WhAll,
         float* __restrict__ C,
         __half* __restrict__ C0h, __half* __restrict__ C0l,
         __half* __restrict__ C1h, __half* __restrict__ C1l,
         __half* __restrict__ C2h, __half* __restrict__ C2l,
         int qkv)
{
    constexpr int K = DM;
    constexpr int TILE  = 10240;   // 128 rows x 40 fp16 (pitch 80B)
    constexpr int STAGE = 3 * TILE;
    extern __shared__ __align__(128) char smg[];
    const uint32_t sbase = s2u(smg);

    const int z   = blockIdx.z;
    const int mode = qkv ? ((z == 2) ? 1 : 2) : 0;
    const float oscale = (qkv && z == 0) ? 0.125f * 1.44269504f : 1.0f;
    const size_t wsel = qkv ? (size_t)z * DM * DM : (size_t)3 * DM * DM;
    const __half* Bh_g = WhAll + wsel;
    __half* Ch = (z == 0) ? C0h : (z == 1) ? C1h : C2h;
    __half* Cl = (z == 0) ? C0l : (z == 1) ? C1l : C2l;

    const int bm  = blockIdx.y * 128;
    const int bn  = blockIdx.x * 128;
    const int tid = threadIdx.x;
    const int lane = tid & 31;
    const int wid  = tid >> 5;
    const int wm = (wid >> 2) * 64;
    const int wn = (wid & 3) * 32;

    const __half* srcs[3] = {
        Ah_g + (size_t)bm * K, Al_g + (size_t)bm * K, Bh_g + (size_t)bn * K };

    auto fill = [&](int s, int kc) {
#pragma unroll
        for (int t = 0; t < 3; ++t) {
#pragma unroll
            for (int i = 0; i < 2; ++i) {
                const int idx = i * 256 + tid;
                const int r = idx >> 2;
                const int c = idx & 3;
                cp16(sbase + s * STAGE + t * TILE + r * 80 + c * 16,
                     srcs[t] + (size_t)r * K + kc * 32 + c * 8);
            }
        }
        CP_COMMIT;
    };

    float acc[4][4][4] = {};

    fill(0, 0);
    for (int kc = 0; kc < K / 32; ++kc) {
        CP_WAIT0;
        __syncthreads();
        if (kc + 1 < K / 32) fill((kc + 1) & 1, kc + 1);

        const uint32_t aB = sbase + (kc & 1) * STAGE;
        const uint32_t bB = aB + 2 * TILE;
#pragma unroll
        for (int ks = 0; ks < 2; ++ks) {
            uint32_t ah[4][4], al[4][4];
#pragma unroll
            for (int mt = 0; mt < 4; ++mt) {
                const uint32_t ad = aB +
                    ((wm + mt * 16 + (lane & 15)) * 40 + ks * 16 + (lane >> 4) * 8) * 2;
                ldsm4(ah[mt], ad);
                ldsm4(al[mt], ad + TILE);
            }
#pragma unroll
            for (int np = 0; np < 2; ++np) {
                uint32_t bh[4];
                const uint32_t ad = bB +
                    ((wn + np * 16 + (lane & 15)) * 40 + ks * 16 + (lane >> 4) * 8) * 2;
                ldsm4(bh, ad);
#pragma unroll
                for (int mt = 0; mt < 4; ++mt)
#pragma unroll
                    for (int hf = 0; hf < 2; ++hf)
                        mma16816(acc[mt][np * 2 + hf], ah[mt], bh[hf], bh[hf + 2]);
#pragma unroll
                for (int mt = 0; mt < 4; ++mt)
#pragma unroll
                    for (int hf = 0; hf < 2; ++hf)
                        mma16816(acc[mt][np * 2 + hf], al[mt], bh[hf], bh[hf + 2]);
            }
        }
        __syncthreads();
    }

#pragma unroll
    for (int mt = 0; mt < 4; ++mt)
#pragma unroll
        for (int ri = 0; ri < 2; ++ri) {
            const int m = bm + wm + mt * 16 + ri * 8 + (lane >> 2);
#pragma unroll
            for (int nt = 0; nt < 4; ++nt) {
                const int n = bn + wn + nt * 8 + 2 * (lane & 3);
                float v0 = acc[mt][nt][ri * 2 + 0];
                float v1 = acc[mt][nt][ri * 2 + 1];
                if (mode == 0) {
                    *(float2*)(C + (size_t)m * DM + n) = make_float2(v0, v1);
                } else {
                    if (mode == 2) {
                        const int d = n & 63;   // even
                        const float inv = exp2f((float)d * -0.20762050f);
                        float sn, cs;
                        sincosf((float)m * inv, &sn, &cs);
                        const float a = v0, b = v1;
                        v0 = (a * cs - b * sn) * oscale;
                        v1 = (b * cs + a * sn) * oscale;
                    }
                    const int hh = n >> 6;
                    const int d0 = n & 63;
                    const size_t off = ((size_t)hh * SEQ + m) * DK + d0;
                    uint32_t h, l;
                    split2(v0, v1, h, l);
                    *(uint32_t*)(Ch + off) = h;
                    *(uint32_t*)(Cl + off) = l;
                }
            }
        }
}

// ---------------------------------------------------------------------------
// FA2-style flash attention, causal, fp16 mma (unchanged from R13).
// Br=128 (8 warps x 16 rows), Bc=64, 2 CTAs/SM. Q pre-scaled by 0.125*log2e.
// S = (Qh+Ql)·Kh 2-term. P via ex2.approx.f16x2; l via ones-column V tile.
// Causal mask hoisted to last 2 iterations.
// ---------------------------------------------------------------------------
#define F_K0  0        // 64x144B, hi only
#define F_K1  9216
#define F_V0  18432    // hi only; bytes 128..143 of each row = ones-column pad
#define F_V1  27648
#define F_Q   36864    // 128x144B hi + lo(+18432)
#define F_TOT 73728

__global__ void __launch_bounds__(256, 2)
flash_tc(const __half* __restrict__ qh, const __half* __restrict__ ql,
         const __half* __restrict__ kh,
         const __half* __restrict__ vh,
         __half* __restrict__ aoh, __half* __restrict__ aol)
{
    extern __shared__ __align__(128) char sma[];
    const uint32_t sbase = s2u(sma);

    const int h    = blockIdx.y;
    const int qb   = gridDim.x - 1 - blockIdx.x;   // heavy tiles first
    const int tid  = threadIdx.x;
    const int lane = tid & 31;
    const int wid  = tid >> 5;
    const int wm   = wid * 16;
    const int g    = lane >> 2;
    const int tq   = lane & 3;

    const size_t hb = (size_t)h * SEQ * DK;
    const int nkb = 2 * qb + 2;     // number of 64-token blocks

    // ---- prologue: Q (group), K0+V0 (group) ----
    {
        const __half* qgh = qh + hb + (size_t)qb * 128 * DK;
        const __half* qgl = ql + hb + (size_t)qb * 128 * DK;
#pragma unroll
        for (int i = 0; i < 4; ++i) {
            const int idx = i * 256 + tid;
            const int r = idx >> 3;
            const int c = idx & 7;
            cp16(sbase + F_Q + r * 144 + c * 16, qgh + r * 64 + c * 8);
            cp16(sbase + F_Q + 18432 + r * 144 + c * 16, qgl + r * 64 + c * 8);
        }
        CP_COMMIT;
        const __half* kgh = kh + hb;
        const __half* vgh = vh + hb;
#pragma unroll
        for (int i = 0; i < 2; ++i) {
            const int idx = i * 256 + tid;
            const int r = idx >> 3;        // 0..63
            const int c = idx & 7;
            cp16(sbase + F_K0 + r * 144 + c * 16, kgh + r * 64 + c * 8);
            cp16(sbase + F_V0 + r * 144 + c * 16, vgh + r * 64 + c * 8);
        }
        CP_COMMIT;
    }
    // ones-column pad for both V buffers (cp.async never touches bytes 128..143)
    if (tid < 128) {
        const int buf = tid >> 6;
        const int r = tid & 63;
        uint4* p = (uint4*)(sma + (buf ? F_V1 : F_V0) + r * 144 + 128);
        *p = make_uint4(0x00003c00u, 0u, 0u, 0u);
    }
    CP_WAIT1;
    __syncthreads();

    // ---- Q fragments (resident all kernel) ----
    uint32_t qfh[4][4], qfl[4][4];
#pragma unroll
    for (int d16 = 0; d16 < 4; ++d16) {
        const uint32_t ad = sbase + F_Q +
            ((wm + (lane & 15)) * 72 + d16 * 16 + (lane >> 4) * 8) * 2;
        ldsm4(qfh[d16], ad);
        ldsm4(qfl[d16], ad + 18432);
    }

    float oacc[8][4] = {};
    float oaccL[4] = {};            // ones-column accumulator: col0 = sum(p)
    float mrow[2] = { -1e30f, -1e30f };

    auto body = [&](int kb, bool domask) {
        __syncthreads();

        // prefetch K,V (kb+1)
        if (kb + 1 < nkb) {
            const __half* kgh = kh + hb + (size_t)(kb + 1) * 64 * DK;
            const __half* vgh = vh + hb + (size_t)(kb + 1) * 64 * DK;
            const uint32_t kB = sbase + (((kb + 1) & 1) ? F_K1 : F_K0);
            const uint32_t vB = sbase + (((kb + 1) & 1) ? F_V1 : F_V0);
#pragma unroll
            for (int i = 0; i < 2; ++i) {
                const int idx = i * 256 + tid;
                const int r = idx >> 3;
                const int c = idx & 7;
                cp16(kB + r * 144 + c * 16, kgh + r * 64 + c * 8);
                cp16(vB + r * 144 + c * 16, vgh + r * 64 + c * 8);
            }
        }
        CP_COMMIT;
        CP_WAIT1;
        __syncthreads();

        const uint32_t kBuf = sbase + ((kb & 1) ? F_K1 : F_K0);
        const uint32_t vBuf = sbase + ((kb & 1) ? F_V1 : F_V0);

        // ---- S = (Qh + Ql) · Kh (2-term) ----
        float sacc[8][4] = {};
#pragma unroll
        for (int d16 = 0; d16 < 4; ++d16) {
#pragma unroll
            for (int ng = 0; ng < 4; ++ng) {
                uint32_t bh[4];
                const uint32_t ad = kBuf +
                    ((ng * 16 + (lane & 15)) * 72 + d16 * 16 + (lane >> 4) * 8) * 2;
                ldsm4(bh, ad);
                mma16816(sacc[2 * ng],     qfh[d16], bh[0], bh[2]);
                mma16816(sacc[2 * ng + 1], qfh[d16], bh[1], bh[3]);
                mma16816(sacc[2 * ng],     qfl[d16], bh[0], bh[2]);
                mma16816(sacc[2 * ng + 1], qfl[d16], bh[1], bh[3]);
            }
        }

        // ---- warp-local online softmax (log2 domain), P -> half2 regs ----
        const int moff = (kb - 2 * qb) * 64;    // used only when domask
        uint32_t ph2[8][2];
        float corr[2];
#pragma unroll
        for (int hf = 0; hf < 2; ++hf) {
            const int rloc = wm + g + hf * 8;
            float vmax = -1e30f;
#pragma unroll
            for (int j = 0; j < 8; ++j)
#pragma unroll
                for (int ci = 0; ci < 2; ++ci) {
                    float v = sacc[j][hf * 2 + ci];
                    if (domask && (moff + 8 * j + 2 * tq + ci) > rloc) {
                        v = -1e30f;
                        sacc[j][hf * 2 + ci] = v;
                    }
                    vmax = fmaxf(vmax, v);
                }
            vmax = fmaxf(vmax, __shfl_xor_sync(0xffffffffu, vmax, 1));
            vmax = fmaxf(vmax, __shfl_xor_sync(0xffffffffu, vmax, 2));
            const float mnew = fmaxf(mrow[hf], vmax);
            corr[hf] = exp2f(mrow[hf] - mnew);
            mrow[hf] = mnew;
#pragma unroll
            for (int j = 0; j < 8; ++j)
                ph2[j][hf] = h2exp2(cvt_h2(sacc[j][hf * 2 + 0] - mnew,
                                           sacc[j][hf * 2 + 1] - mnew));
#pragma unroll
            for (int j = 0; j < 8; ++j) {
                oacc[j][hf * 2 + 0] *= corr[hf];
                oacc[j][hf * 2 + 1] *= corr[hf];
            }
            oaccL[hf * 2 + 0] *= corr[hf];
            oaccL[hf * 2 + 1] *= corr[hf];
        }

        // ---- O += P V ; l += P·1 (ones column) ----
#pragma unroll
        for (int kt = 0; kt < 4; ++kt) {
            uint32_t ah[4];
            ah[0] = ph2[2 * kt][0];
            ah[1] = ph2[2 * kt][1];
            ah[2] = ph2[2 * kt + 1][0];
            ah[3] = ph2[2 * kt + 1][1];
            const int t_loc = kt * 16 + (lane & 7) + ((lane >> 3) & 1) * 8;
#pragma unroll
            for (int ng = 0; ng < 4; ++ng) {
                uint32_t bh[4];
                const int d_loc = ng * 16 + ((lane >> 4) & 1) * 8;
                const uint32_t ad = vBuf + (uint32_t)(t_loc * 72 + d_loc) * 2;
                ldsm4t(bh, ad);
                mma16816(oacc[2 * ng],     ah, bh[0], bh[1]);
                mma16816(oacc[2 * ng + 1], ah, bh[2], bh[3]);
            }
            {
                uint32_t bo[2];
                ldsm2t(bo, vBuf + (uint32_t)(t_loc * 72 + 64) * 2);
                mma16816(oaccL, ah, bo[0], bo[1]);
            }
        }
    };

    for (int kb = 0; kb < nkb - 2; ++kb) body(kb, false);
    body(nkb - 2, true);
    body(nkb - 1, true);

    // ---- epilogue: l from ones-column (col 0 -> tq==0), broadcast in quad ----
#pragma unroll
    for (int hf = 0; hf < 2; ++hf) {
        const float lv = __shfl_sync(0xffffffffu, oaccL[hf * 2 + 0], lane & ~3);
        const float inv = 1.f / lv;
        const int q = qb * 128 + wm + g + hf * 8;
#pragma unroll
        for (int j = 0; j < 8; ++j) {
            const float v0 = oacc[j][hf * 2 + 0] * inv;
            const float v1 = oacc[j][hf * 2 + 1] * inv;
            const int col = h * 64 + 8 * j + 2 * tq;
            uint32_t hw, lw;
            split2(v0, v1, hw, lw);
            *(uint32_t*)(aoh + (size_t)q * DM + col) = hw;
            *(uint32_t*)(aol + (size_t)q * DM + col) = lw;
        }
    }
}

// ---------------------------------------------------------------------------
extern "C" void kernel_launch(void* const* d_in, const int* in_sizes, int n_in,
                              void* d_out, int out_size)
{
    const float* x  = (const float*)d_in[0];
    const float* Wq = (const float*)d_in[1];
    const float* Wk = (const float*)d_in[2];
    const float* Wv = (const float*)d_in[3];
    const float* Wo = (const float*)d_in[4];

    __half *xh, *xl, *wh, *qhp, *qlp, *khp, *klp, *vhp, *aoh, *aol;
    cudaGetSymbolAddress((void**)&xh,  g_xh);
    cudaGetSymbolAddress((void**)&xl,  g_xl);
    cudaGetSymbolAddress((void**)&wh,  g_wh);
    cudaGetSymbolAddress((void**)&qhp, g_qh);
    cudaGetSymbolAddress((void**)&qlp, g_ql);
    cudaGetSymbolAddress((void**)&khp, g_kh);
    cudaGetSymbolAddress((void**)&klp, g_kl);
    cudaGetSymbolAddress((void**)&vhp, g_vh);
    cudaGetSymbolAddress((void**)&aoh, g_aoh);
    cudaGetSymbolAddress((void**)&aol, g_aol);

    const int nx2 = SEQ * DM / 2;
    const int nw2 = DM * DM / 2;
    split_bf16<<<(nx2 + 255) / 256, 256>>>(x, xh, xl, nx2);
    cvt4_f16<<<dim3((nw2 + 255) / 256, 4), 256>>>(Wq, Wk, Wv, Wo, wh, nw2);

    const int gsm = 2 * 3 * 10240;   // 61,440 B
    cudaFuncSetAttribute(gemm_mma, cudaFuncAttributeMaxDynamicSharedMemorySize, gsm);
    cudaFuncSetAttribute(flash_tc, cudaFuncAttributeMaxDynamicSharedMemorySize, F_TOT);

    // fused Q/K/V projections (Q pre-scaled by 0.125*log2e); K lo and V lo are
    // not consumed by flash — klp / aol are dummy targets (aol fully
    // overwritten by the flash epilogue afterwards).
    gemm_mma<<<dim3(DM / 128, SEQ / 128, 3), 256, gsm>>>(
        xh, xl, wh, nullptr, qhp, qlp, khp, klp, vhp, aol, 1);

    flash_tc<<<dim3(SEQ / 128, NH), 256, F_TOT>>>(qhp, qlp, khp, vhp, aoh, aol);

    // Wo projection (2-term, weights hi only)
    gemm_mma<<<dim3(DM / 128, SEQ / 128, 1), 256, gsm>>>(
        aoh, aol, wh, (float*)d_out,
        nullptr, nullptr, nullptr, nullptr, nullptr, nullptr, 0);
}

// round 15
// speedup vs baseline: 1.4218x; 1.1358x over previous
#include <cuda_runtime.h>
#include <cuda_fp16.h>
#include <math.h>
#include <stdint.h>

#define SEQ 4096
#define DM  1024
#define NH  16
#define DK  64

// ---------------------------------------------------------------------------
// scratch (no allocs allowed)
// ---------------------------------------------------------------------------
__device__ __half g_xh [SEQ * DM];
__device__ __half g_xl [SEQ * DM];
__device__ __half g_wh [4][DM * DM];
__device__ __half g_qh [NH * SEQ * DK];
__device__ __half g_ql [NH * SEQ * DK];
__device__ __half g_kh [NH * SEQ * DK];
__device__ __half g_kl [NH * SEQ * DK];   // written by z=1 epilogue, unused
__device__ __half g_vh [NH * SEQ * DK];
__device__ __half g_vl [NH * SEQ * DK];   // dummy target
__device__ __half g_aoh[SEQ * DM];

// ---------------------------------------------------------------------------
// helpers
// ---------------------------------------------------------------------------
static __device__ __forceinline__ uint32_t s2u(const void* p) {
    uint32_t a;
    asm("{ .reg .u64 t; cvta.to.shared.u64 t, %1; cvt.u32.u64 %0, t; }"
        : "=r"(a) : "l"(p));
    return a;
}
static __device__ __forceinline__ void ldsm4(uint32_t* r, uint32_t addr) {
    asm volatile("ldmatrix.sync.aligned.m8n8.x4.shared.b16 {%0,%1,%2,%3}, [%4];"
                 : "=r"(r[0]), "=r"(r[1]), "=r"(r[2]), "=r"(r[3]) : "r"(addr));
}
static __device__ __forceinline__ void ldsm4t(uint32_t* r, uint32_t addr) {
    asm volatile("ldmatrix.sync.aligned.m8n8.x4.trans.shared.b16 {%0,%1,%2,%3}, [%4];"
                 : "=r"(r[0]), "=r"(r[1]), "=r"(r[2]), "=r"(r[3]) : "r"(addr));
}
static __device__ __forceinline__ void ldsm2t(uint32_t* r, uint32_t addr) {
    asm volatile("ldmatrix.sync.aligned.m8n8.x2.trans.shared.b16 {%0,%1}, [%2];"
                 : "=r"(r[0]), "=r"(r[1]) : "r"(addr));
}
static __device__ __forceinline__ void mma16816(float* d, const uint32_t* a,
                                                uint32_t b0, uint32_t b1) {
    asm volatile(
        "mma.sync.aligned.m16n8k16.row.col.f32.f16.f16.f32 "
        "{%0,%1,%2,%3},{%4,%5,%6,%7},{%8,%9},{%0,%1,%2,%3};"
        : "+f"(d[0]), "+f"(d[1]), "+f"(d[2]), "+f"(d[3])
        : "r"(a[0]), "r"(a[1]), "r"(a[2]), "r"(a[3]), "r"(b0), "r"(b1));
}
static __device__ __forceinline__ void cp16(uint32_t s, const void* g) {
    asm volatile("cp.async.cg.shared.global [%0], [%1], 16;" :: "r"(s), "l"(g));
}
#define CP_COMMIT asm volatile("cp.async.commit_group;")
#define CP_WAIT0  asm volatile("cp.async.wait_group 0;")
#define CP_WAIT1  asm volatile("cp.async.wait_group 1;")

static __device__ __forceinline__ uint32_t pack_h2(__half a, __half b) {
    __half2 t = __halves2half2(a, b);
    return *reinterpret_cast<uint32_t*>(&t);
}
static __device__ __forceinline__ uint32_t cvt_h2(float lo, float hi) {
    uint32_t r;
    asm("cvt.rn.f16x2.f32 %0, %1, %2;" : "=r"(r) : "f"(hi), "f"(lo));
    return r;
}
static __device__ __forceinline__ uint32_t h2exp2(uint32_t x) {
    uint32_t r;
    asm("ex2.approx.f16x2 %0, %1;" : "=r"(r) : "r"(x));
    return r;
}
static __device__ __forceinline__ void split2(float v0, float v1,
                                              uint32_t& hi, uint32_t& lo) {
    __half h0 = __float2half_rn(v0);
    __half h1 = __float2half_rn(v1);
    __half l0 = __float2half_rn(v0 - __half2float(h0));
    __half l1 = __float2half_rn(v1 - __half2float(h1));
    hi = pack_h2(h0, h1);
    lo = pack_h2(l0, l1);
}

// ---------------------------------------------------------------------------
// split fp32 -> fp16 (hi, lo) for x; weights: hi-only convert (4 at once)
// ---------------------------------------------------------------------------
__global__ void __launch_bounds__(256)
split_bf16(const float* __restrict__ src, __half* __restrict__ hi,
           __half* __restrict__ lo, int n2)
{
    int i = blockIdx.x * 256 + threadIdx.x;
    if (i >= n2) return;
    float2 v = ((const float2*)src)[i];
    uint32_t h, l;
    split2(v.x, v.y, h, l);
    ((uint32_t*)hi)[i] = h;
    ((uint32_t*)lo)[i] = l;
}

__global__ void __launch_bounds__(256)
cvt4_f16(const float* __restrict__ s0, const float* __restrict__ s1,
         const float* __restrict__ s2, const float* __restrict__ s3,
         __half* __restrict__ hi, int n2)
{
    int i = blockIdx.x * 256 + threadIdx.x;
    if (i >= n2) return;
    const int y = blockIdx.y;
    const float* s = (y == 0) ? s0 : (y == 1) ? s1 : (y == 2) ? s2 : s3;
    float2 v = ((const float2*)s)[i];
    ((uint32_t*)hi)[(size_t)y * (DM * DM / 2) + i] = cvt_h2(v.x, v.y);
}

// ---------------------------------------------------------------------------
// mma.sync fp16 GEMM: C = (Ah [+ Al]) · Bh^T. 128x128x32 tiles,
// cp.async double-buffered (2-3 tiles/stage), 8 warps (2m x 4n), 2 CTAs/SM.
// Q,K projections (z<2): 2-term (Ah+Al). V projection & Wo: 1-term (Ah only).
// Q output (z==0) pre-scaled by 0.125*log2(e).
// ---------------------------------------------------------------------------
__global__ void __launch_bounds__(256, 2)
gemm_mma(const __half* __restrict__ Ah_g, const __half* __restrict__ Al_g,
         const __half* __restrict__ WhAll,
         float* __restrict__ C,
         __half* __restrict__ C0h, __half* __restrict__ C0l,
         __half* __restrict__ C1h, __half* __restrict__ C1l,
         __half* __restrict__ C2h, __half* __restrict__ C2l,
         int qkv)
{
    constexpr int K = DM;
    constexpr int TILE  = 10240;   // 128 rows x 40 fp16 (pitch 80B)
    constexpr int STAGE = 3 * TILE;
    extern __shared__ __align__(128) char smg[];
    const uint32_t sbase = s2u(smg);

    const int z   = blockIdx.z;
    const int mode = qkv ? ((z == 2) ? 1 : 2) : 0;
    const bool useAl = qkv && (z < 2);     // 2-term only for Q,K
    const float oscale = (qkv && z == 0) ? 0.125f * 1.44269504f : 1.0f;
    const size_t wsel = qkv ? (size_t)z * DM * DM : (size_t)3 * DM * DM;
    const __half* Bh_g = WhAll + wsel;
    __half* Ch = (z == 0) ? C0h : (z == 1) ? C1h : C2h;
    __half* Cl = (z == 0) ? C0l : (z == 1) ? C1l : C2l;

    const int bm  = blockIdx.y * 128;
    const int bn  = blockIdx.x * 128;
    const int tid = threadIdx.x;
    const int lane = tid & 31;
    const int wid  = tid >> 5;
    const int wm = (wid >> 2) * 64;
    const int wn = (wid & 3) * 32;

    const __half* srcs[3] = {
        Ah_g + (size_t)bm * K, Al_g + (size_t)bm * K, Bh_g + (size_t)bn * K };

    auto fill = [&](int s, int kc) {
#pragma unroll
        for (int t = 0; t < 3; ++t) {
            if (t == 1 && !useAl) continue;
#pragma unroll
            for (int i = 0; i < 2; ++i) {
                const int idx = i * 256 + tid;
                const int r = idx >> 2;
                const int c = idx & 3;
                cp16(sbase + s * STAGE + t * TILE + r * 80 + c * 16,
                     srcs[t] + (size_t)r * K + kc * 32 + c * 8);
            }
        }
        CP_COMMIT;
    };

    float acc[4][4][4] = {};

    fill(0, 0);
    for (int kc = 0; kc < K / 32; ++kc) {
        CP_WAIT0;
        __syncthreads();
        if (kc + 1 < K / 32) fill((kc + 1) & 1, kc + 1);

        const uint32_t aB = sbase + (kc & 1) * STAGE;
        const uint32_t bB = aB + 2 * TILE;
#pragma unroll
        for (int ks = 0; ks < 2; ++ks) {
            uint32_t ah[4][4], al[4][4];
#pragma unroll
            for (int mt = 0; mt < 4; ++mt) {
                const uint32_t ad = aB +
                    ((wm + mt * 16 + (lane & 15)) * 40 + ks * 16 + (lane >> 4) * 8) * 2;
                ldsm4(ah[mt], ad);
                if (useAl) ldsm4(al[mt], ad + TILE);
            }
#pragma unroll
            for (int np = 0; np < 2; ++np) {
                uint32_t bh[4];
                const uint32_t ad = bB +
                    ((wn + np * 16 + (lane & 15)) * 40 + ks * 16 + (lane >> 4) * 8) * 2;
                ldsm4(bh, ad);
#pragma unroll
                for (int mt = 0; mt < 4; ++mt)
#pragma unroll
                    for (int hf = 0; hf < 2; ++hf)
                        mma16816(acc[mt][np * 2 + hf], ah[mt], bh[hf], bh[hf + 2]);
                if (useAl) {
#pragma unroll
                    for (int mt = 0; mt < 4; ++mt)
#pragma unroll
                        for (int hf = 0; hf < 2; ++hf)
                            mma16816(acc[mt][np * 2 + hf], al[mt], bh[hf], bh[hf + 2]);
                }
            }
        }
        __syncthreads();
    }

#pragma unroll
    for (int mt = 0; mt < 4; ++mt)
#pragma unroll
        for (int ri = 0; ri < 2; ++ri) {
            const int m = bm + wm + mt * 16 + ri * 8 + (lane >> 2);
#pragma unroll
            for (int nt = 0; nt < 4; ++nt) {
                const int n = bn + wn + nt * 8 + 2 * (lane & 3);
                float v0 = acc[mt][nt][ri * 2 + 0];
                float v1 = acc[mt][nt][ri * 2 + 1];
                if (mode == 0) {
                    *(float2*)(C + (size_t)m * DM + n) = make_float2(v0, v1);
                } else {
                    if (mode == 2) {
                        const int d = n & 63;   // even
                        const float inv = exp2f((float)d * -0.20762050f);
                        float sn, cs;
                        sincosf((float)m * inv, &sn, &cs);
                        const float a = v0, b = v1;
                        v0 = (a * cs - b * sn) * oscale;
                        v1 = (b * cs + a * sn) * oscale;
                    }
                    const int hh = n >> 6;
                    const int d0 = n & 63;
                    const size_t off = ((size_t)hh * SEQ + m) * DK + d0;
                    uint32_t h, l;
                    split2(v0, v1, h, l);
                    *(uint32_t*)(Ch + off) = h;
                    *(uint32_t*)(Cl + off) = l;
                }
            }
        }
}

// ---------------------------------------------------------------------------
// FA2-style flash attention, causal, fp16 mma.
// Br=128 (8 warps x 16 rows), Bc=64, 2 CTAs/SM. Q pre-scaled by 0.125*log2e.
// S = (Qh+Ql)·Kh 2-term. P via ex2.approx.f16x2; l via ones-column V tile.
// Causal mask hoisted to last 2 iterations. Output: single fp16 (aoh).
// ---------------------------------------------------------------------------
#define F_K0  0        // 64x144B, hi only
#define F_K1  9216
#define F_V0  18432    // hi only; bytes 128..143 of each row = ones-column pad
#define F_V1  27648
#define F_Q   36864    // 128x144B hi + lo(+18432)
#define F_TOT 73728

__global__ void __launch_bounds__(256, 2)
flash_tc(const __half* __restrict__ qh, const __half* __restrict__ ql,
         const __half* __restrict__ kh,
         const __half* __restrict__ vh,
         __half* __restrict__ aoh)
{
    extern __shared__ __align__(128) char sma[];
    const uint32_t sbase = s2u(sma);

    const int h    = blockIdx.y;
    const int qb   = gridDim.x - 1 - blockIdx.x;   // heavy tiles first
    const int tid  = threadIdx.x;
    const int lane = tid & 31;
    const int wid  = tid >> 5;
    const int wm   = wid * 16;
    const int g    = lane >> 2;
    const int tq   = lane & 3;

    const size_t hb = (size_t)h * SEQ * DK;
    const int nkb = 2 * qb + 2;     // number of 64-token blocks

    // ---- prologue: Q (group), K0+V0 (group) ----
    {
        const __half* qgh = qh + hb + (size_t)qb * 128 * DK;
        const __half* qgl = ql + hb + (size_t)qb * 128 * DK;
#pragma unroll
        for (int i = 0; i < 4; ++i) {
            const int idx = i * 256 + tid;
            const int r = idx >> 3;
            const int c = idx & 7;
            cp16(sbase + F_Q + r * 144 + c * 16, qgh + r * 64 + c * 8);
            cp16(sbase + F_Q + 18432 + r * 144 + c * 16, qgl + r * 64 + c * 8);
        }
        CP_COMMIT;
        const __half* kgh = kh + hb;
        const __half* vgh = vh + hb;
#pragma unroll
        for (int i = 0; i < 2; ++i) {
            const int idx = i * 256 + tid;
            const int r = idx >> 3;        // 0..63
            const int c = idx & 7;
            cp16(sbase + F_K0 + r * 144 + c * 16, kgh + r * 64 + c * 8);
            cp16(sbase + F_V0 + r * 144 + c * 16, vgh + r * 64 + c * 8);
        }
        CP_COMMIT;
    }
    // ones-column pad for both V buffers (cp.async never touches bytes 128..143)
    if (tid < 128) {
        const int buf = tid >> 6;
        const int r = tid & 63;
        uint4* p = (uint4*)(sma + (buf ? F_V1 : F_V0) + r * 144 + 128);
        *p = make_uint4(0x00003c00u, 0u, 0u, 0u);
    }
    CP_WAIT1;
    __syncthreads();

    // ---- Q fragments (resident all kernel) ----
    uint32_t qfh[4][4], qfl[4][4];
#pragma unroll
    for (int d16 = 0; d16 < 4; ++d16) {
        const uint32_t ad = sbase + F_Q +
            ((wm + (lane & 15)) * 72 + d16 * 16 + (lane >> 4) * 8) * 2;
        ldsm4(qfh[d16], ad);
        ldsm4(qfl[d16], ad + 18432);
    }

    float oacc[8][4] = {};
    float oaccL[4] = {};            // ones-column accumulator: col0 = sum(p)
    float mrow[2] = { -1e30f, -1e30f };

    auto body = [&](int kb, bool domask) {
        __syncthreads();

        // prefetch K,V (kb+1)
        if (kb + 1 < nkb) {
            const __half* kgh = kh + hb + (size_t)(kb + 1) * 64 * DK;
            const __half* vgh = vh + hb + (size_t)(kb + 1) * 64 * DK;
            const uint32_t kB = sbase + (((kb + 1) & 1) ? F_K1 : F_K0);
            const uint32_t vB = sbase + (((kb + 1) & 1) ? F_V1 : F_V0);
#pragma unroll
            for (int i = 0; i < 2; ++i) {
                const int idx = i * 256 + tid;
                const int r = idx >> 3;
                const int c = idx & 7;
                cp16(kB + r * 144 + c * 16, kgh + r * 64 + c * 8);
                cp16(vB + r * 144 + c * 16, vgh + r * 64 + c * 8);
            }
        }
        CP_COMMIT;
        CP_WAIT1;
        __syncthreads();

        const uint32_t kBuf = sbase + ((kb & 1) ? F_K1 : F_K0);
        const uint32_t vBuf = sbase + ((kb & 1) ? F_V1 : F_V0);

        // ---- S = (Qh + Ql) · Kh (2-term) ----
        float sacc[8][4] = {};
#pragma unroll
        for (int d16 = 0; d16 < 4; ++d16) {
#pragma unroll
            for (int ng = 0; ng < 4; ++ng) {
                uint32_t bh[4];
                const uint32_t ad = kBuf +
                    ((ng * 16 + (lane & 15)) * 72 + d16 * 16 + (lane >> 4) * 8) * 2;
                ldsm4(bh, ad);
                mma16816(sacc[2 * ng],     qfh[d16], bh[0], bh[2]);
                mma16816(sacc[2 * ng + 1], qfh[d16], bh[1], bh[3]);
                mma16816(sacc[2 * ng],     qfl[d16], bh[0], bh[2]);
                mma16816(sacc[2 * ng + 1], qfl[d16], bh[1], bh[3]);
            }
        }

        // ---- warp-local online softmax (log2 domain), P -> half2 regs ----
        const int moff = (kb - 2 * qb) * 64;    // used only when domask
        uint32_t ph2[8][2];
        float corr[2];
#pragma unroll
        for (int hf = 0; hf < 2; ++hf) {
            const int rloc = wm + g + hf * 8;
            float vmax = -1e30f;
#pragma unroll
            for (int j = 0; j < 8; ++j)
#pragma unroll
                for (int ci = 0; ci < 2; ++ci) {
                    float v = sacc[j][hf * 2 + ci];
                    if (domask && (moff + 8 * j + 2 * tq + ci) > rloc) {
                        v = -1e30f;
                        sacc[j][hf * 2 + ci] = v;
                    }
                    vmax = fmaxf(vmax, v);
                }
            vmax = fmaxf(vmax, __shfl_xor_sync(0xffffffffu, vmax, 1));
            vmax = fmaxf(vmax, __shfl_xor_sync(0xffffffffu, vmax, 2));
            const float mnew = fmaxf(mrow[hf], vmax);
            corr[hf] = exp2f(mrow[hf] - mnew);
            mrow[hf] = mnew;
#pragma unroll
            for (int j = 0; j < 8; ++j)
                ph2[j][hf] = h2exp2(cvt_h2(sacc[j][hf * 2 + 0] - mnew,
                                           sacc[j][hf * 2 + 1] - mnew));
#pragma unroll
            for (int j = 0; j < 8; ++j) {
                oacc[j][hf * 2 + 0] *= corr[hf];
                oacc[j][hf * 2 + 1] *= corr[hf];
            }
            oaccL[hf * 2 + 0] *= corr[hf];
            oaccL[hf * 2 + 1] *= corr[hf];
        }

        // ---- O += P V ; l += P·1 (ones column) ----
#pragma unroll
        for (int kt = 0; kt < 4; ++kt) {
            uint32_t ah[4];
            ah[0] = ph2[2 * kt][0];
            ah[1] = ph2[2 * kt][1];
            ah[2] = ph2[2 * kt + 1][0];
            ah[3] = ph2[2 * kt + 1][1];
            const int t_loc = kt * 16 + (lane & 7) + ((lane >> 3) & 1) * 8;
#pragma unroll
            for (int ng = 0; ng < 4; ++ng) {
                uint32_t bh[4];
                const int d_loc = ng * 16 + ((lane >> 4) & 1) * 8;
                const uint32_t ad = vBuf + (uint32_t)(t_loc * 72 + d_loc) * 2;
                ldsm4t(bh, ad);
                mma16816(oacc[2 * ng],     ah, bh[0], bh[1]);
                mma16816(oacc[2 * ng + 1], ah, bh[2], bh[3]);
            }
            {
                uint32_t bo[2];
                ldsm2t(bo, vBuf + (uint32_t)(t_loc * 72 + 64) * 2);
                mma16816(oaccL, ah, bo[0], bo[1]);
            }
        }
    };

    for (int kb = 0; kb < nkb - 2; ++kb) body(kb, false);
    body(nkb - 2, true);
    body(nkb - 1, true);

    // ---- epilogue: l from ones-column, single fp16 output ----
#pragma unroll
    for (int hf = 0; hf < 2; ++hf) {
        const float lv = __shfl_sync(0xffffffffu, oaccL[hf * 2 + 0], lane & ~3);
        const float inv = 1.f / lv;
        const int q = qb * 128 + wm + g + hf * 8;
#pragma unroll
        for (int j = 0; j < 8; ++j) {
            const float v0 = oacc[j][hf * 2 + 0] * inv;
            const float v1 = oacc[j][hf * 2 + 1] * inv;
            const int col = h * 64 + 8 * j + 2 * tq;
            *(uint32_t*)(aoh + (size_t)q * DM + col) = cvt_h2(v0, v1);
        }
    }
}

// ---------------------------------------------------------------------------
extern "C" void kernel_launch(void* const* d_in, const int* in_sizes, int n_in,
                              void* d_out, int out_size)
{
    const float* x  = (const float*)d_in[0];
    const float* Wq = (const float*)d_in[1];
    const float* Wk = (const float*)d_in[2];
    const float* Wv = (const float*)d_in[3];
    const float* Wo = (const float*)d_in[4];

    __half *xh, *xl, *wh, *qhp, *qlp, *khp, *klp, *vhp, *vlp, *aoh;
    cudaGetSymbolAddress((void**)&xh,  g_xh);
    cudaGetSymbolAddress((void**)&xl,  g_xl);
    cudaGetSymbolAddress((void**)&wh,  g_wh);
    cudaGetSymbolAddress((void**)&qhp, g_qh);
    cudaGetSymbolAddress((void**)&qlp, g_ql);
    cudaGetSymbolAddress((void**)&khp, g_kh);
    cudaGetSymbolAddress((void**)&klp, g_kl);
    cudaGetSymbolAddress((void**)&vhp, g_vh);
    cudaGetSymbolAddress((void**)&vlp, g_vl);
    cudaGetSymbolAddress((void**)&aoh, g_aoh);

    const int nx2 = SEQ * DM / 2;
    const int nw2 = DM * DM / 2;
    split_bf16<<<(nx2 + 255) / 256, 256>>>(x, xh, xl, nx2);
    cvt4_f16<<<dim3((nw2 + 255) / 256, 4), 256>>>(Wq, Wk, Wv, Wo, wh, nw2);

    const int gsm = 2 * 3 * 10240;   // 61,440 B
    cudaFuncSetAttribute(gemm_mma, cudaFuncAttributeMaxDynamicSharedMemorySize, gsm);
    cudaFuncSetAttribute(flash_tc, cudaFuncAttributeMaxDynamicSharedMemorySize, F_TOT);

    // fused Q/K/V projections (Q pre-scaled by 0.125*log2e; V 1-term).
    // K lo / V lo go to klp / vlp (not consumed downstream).
    gemm_mma<<<dim3(DM / 128, SEQ / 128, 3), 256, gsm>>>(
        xh, xl, wh, nullptr, qhp, qlp, khp, klp, vhp, vlp, 1);

    flash_tc<<<dim3(SEQ / 128, NH), 256, F_TOT>>>(qhp, qlp, khp, vhp, aoh);

    // Wo projection (1-term)
    gemm_mma<<<dim3(DM / 128, SEQ / 128, 1), 256, gsm>>>(
        aoh, nullptr, wh, (float*)d_out,
        nullptr, nullptr, nullptr, nullptr, nullptr, nullptr, 0);
}

// round 16
// speedup vs baseline: 1.8863x; 1.3267x over previous
#include <cuda_runtime.h>
#include <cuda_fp16.h>
#include <math.h>
#include <stdint.h>

#define SEQ 4096
#define DM  1024
#define NH  16
#define DK  64

// ---------------------------------------------------------------------------
// scratch (no allocs allowed) — everything plain fp16 now
// ---------------------------------------------------------------------------
__device__ __half g_xh [SEQ * DM];
__device__ __half g_wh [4][DM * DM];
__device__ __half g_qh [NH * SEQ * DK];
__device__ __half g_kh [NH * SEQ * DK];
__device__ __half g_vh [NH * SEQ * DK];
__device__ __half g_aoh[SEQ * DM];

// ---------------------------------------------------------------------------
// helpers
// ---------------------------------------------------------------------------
static __device__ __forceinline__ uint32_t s2u(const void* p) {
    uint32_t a;
    asm("{ .reg .u64 t; cvta.to.shared.u64 t, %1; cvt.u32.u64 %0, t; }"
        : "=r"(a) : "l"(p));
    return a;
}
static __device__ __forceinline__ void ldsm4(uint32_t* r, uint32_t addr) {
    asm volatile("ldmatrix.sync.aligned.m8n8.x4.shared.b16 {%0,%1,%2,%3}, [%4];"
                 : "=r"(r[0]), "=r"(r[1]), "=r"(r[2]), "=r"(r[3]) : "r"(addr));
}
static __device__ __forceinline__ void ldsm4t(uint32_t* r, uint32_t addr) {
    asm volatile("ldmatrix.sync.aligned.m8n8.x4.trans.shared.b16 {%0,%1,%2,%3}, [%4];"
                 : "=r"(r[0]), "=r"(r[1]), "=r"(r[2]), "=r"(r[3]) : "r"(addr));
}
static __device__ __forceinline__ void ldsm2t(uint32_t* r, uint32_t addr) {
    asm volatile("ldmatrix.sync.aligned.m8n8.x2.trans.shared.b16 {%0,%1}, [%2];"
                 : "=r"(r[0]), "=r"(r[1]) : "r"(addr));
}
static __device__ __forceinline__ void mma16816(float* d, const uint32_t* a,
                                                uint32_t b0, uint32_t b1) {
    asm volatile(
        "mma.sync.aligned.m16n8k16.row.col.f32.f16.f16.f32 "
        "{%0,%1,%2,%3},{%4,%5,%6,%7},{%8,%9},{%0,%1,%2,%3};"
        : "+f"(d[0]), "+f"(d[1]), "+f"(d[2]), "+f"(d[3])
        : "r"(a[0]), "r"(a[1]), "r"(a[2]), "r"(a[3]), "r"(b0), "r"(b1));
}
static __device__ __forceinline__ void cp16(uint32_t s, const void* g) {
    asm volatile("cp.async.cg.shared.global [%0], [%1], 16;" :: "r"(s), "l"(g));
}
#define CP_COMMIT asm volatile("cp.async.commit_group;")
#define CP_WAIT0  asm volatile("cp.async.wait_group 0;")
#define CP_WAIT1  asm volatile("cp.async.wait_group 1;")

static __device__ __forceinline__ uint32_t cvt_h2(float lo, float hi) {
    uint32_t r;
    asm("cvt.rn.f16x2.f32 %0, %1, %2;" : "=r"(r) : "f"(hi), "f"(lo));
    return r;
}
static __device__ __forceinline__ uint32_t h2exp2(uint32_t x) {
    uint32_t r;
    asm("ex2.approx.f16x2 %0, %1;" : "=r"(r) : "r"(x));
    return r;
}

// ---------------------------------------------------------------------------
// converts: x -> fp16 (1 launch), 4 weights -> fp16 (1 launch)
// ---------------------------------------------------------------------------
__global__ void __launch_bounds__(256)
cvt_f16(const float* __restrict__ src, __half* __restrict__ dst, int n2)
{
    int i = blockIdx.x * 256 + threadIdx.x;
    if (i >= n2) return;
    float2 v = ((const float2*)src)[i];
    ((uint32_t*)dst)[i] = cvt_h2(v.x, v.y);
}

__global__ void __launch_bounds__(256)
cvt4_f16(const float* __restrict__ s0, const float* __restrict__ s1,
         const float* __restrict__ s2, const float* __restrict__ s3,
         __half* __restrict__ dst, int n2)
{
    int i = blockIdx.x * 256 + threadIdx.x;
    if (i >= n2) return;
    const int y = blockIdx.y;
    const float* s = (y == 0) ? s0 : (y == 1) ? s1 : (y == 2) ? s2 : s3;
    float2 v = ((const float2*)s)[i];
    ((uint32_t*)dst)[(size_t)y * (DM * DM / 2) + i] = cvt_h2(v.x, v.y);
}

// ---------------------------------------------------------------------------
// mma.sync fp16 GEMM: C = A · B^T (both fp16). 128x128x32 tiles,
// cp.async double-buffered (2 tiles/stage, 40KB), 8 warps (2m x 4n), 2 CTAs/SM.
// qkv!=0: z selects weight; z==0 output scaled by 0.125*log2(e), RoPE+head;
// z==1 RoPE+head; z==2 head. qkv==0: plain fp32 out with weight 3 (Wo).
// ---------------------------------------------------------------------------
__global__ void __launch_bounds__(256, 2)
gemm_mma(const __half* __restrict__ A_g, const __half* __restrict__ WhAll,
         float* __restrict__ C,
         __half* __restrict__ C0h, __half* __restrict__ C1h, __half* __restrict__ C2h,
         int qkv)
{
    constexpr int K = DM;
    constexpr int TILE  = 10240;   // 128 rows x 40 fp16 (pitch 80B)
    constexpr int STAGE = 2 * TILE;
    extern __shared__ __align__(128) char smg[];
    const uint32_t sbase = s2u(smg);

    const int z   = blockIdx.z;
    const int mode = qkv ? ((z == 2) ? 1 : 2) : 0;
    const float oscale = (qkv && z == 0) ? 0.125f * 1.44269504f : 1.0f;
    const size_t wsel = qkv ? (size_t)z * DM * DM : (size_t)3 * DM * DM;
    const __half* B_g = WhAll + wsel;
    __half* Ch = (z == 0) ? C0h : (z == 1) ? C1h : C2h;

    const int bm  = blockIdx.y * 128;
    const int bn  = blockIdx.x * 128;
    const int tid = threadIdx.x;
    const int lane = tid & 31;
    const int wid  = tid >> 5;
    const int wm = (wid >> 2) * 64;
    const int wn = (wid & 3) * 32;

    const __half* srcs[2] = { A_g + (size_t)bm * K, B_g + (size_t)bn * K };

    auto fill = [&](int s, int kc) {
#pragma unroll
        for (int t = 0; t < 2; ++t) {
#pragma unroll
            for (int i = 0; i < 2; ++i) {
                const int idx = i * 256 + tid;
                const int r = idx >> 2;
                const int c = idx & 3;
                cp16(sbase + s * STAGE + t * TILE + r * 80 + c * 16,
                     srcs[t] + (size_t)r * K + kc * 32 + c * 8);
            }
        }
        CP_COMMIT;
    };

    float acc[4][4][4] = {};

    fill(0, 0);
    for (int kc = 0; kc < K / 32; ++kc) {
        CP_WAIT0;
        __syncthreads();
        if (kc + 1 < K / 32) fill((kc + 1) & 1, kc + 1);

        const uint32_t aB = sbase + (kc & 1) * STAGE;
        const uint32_t bB = aB + TILE;
#pragma unroll
        for (int ks = 0; ks < 2; ++ks) {
            uint32_t ah[4][4];
#pragma unroll
            for (int mt = 0; mt < 4; ++mt) {
                const uint32_t ad = aB +
                    ((wm + mt * 16 + (lane & 15)) * 40 + ks * 16 + (lane >> 4) * 8) * 2;
                ldsm4(ah[mt], ad);
            }
#pragma unroll
            for (int np = 0; np < 2; ++np) {
                uint32_t bh[4];
                const uint32_t ad = bB +
                    ((wn + np * 16 + (lane & 15)) * 40 + ks * 16 + (lane >> 4) * 8) * 2;
                ldsm4(bh, ad);
#pragma unroll
                for (int mt = 0; mt < 4; ++mt)
#pragma unroll
                    for (int hf = 0; hf < 2; ++hf)
                        mma16816(acc[mt][np * 2 + hf], ah[mt], bh[hf], bh[hf + 2]);
            }
        }
        __syncthreads();
    }

#pragma unroll
    for (int mt = 0; mt < 4; ++mt)
#pragma unroll
        for (int ri = 0; ri < 2; ++ri) {
            const int m = bm + wm + mt * 16 + ri * 8 + (lane >> 2);
#pragma unroll
            for (int nt = 0; nt < 4; ++nt) {
                const int n = bn + wn + nt * 8 + 2 * (lane & 3);
                float v0 = acc[mt][nt][ri * 2 + 0];
                float v1 = acc[mt][nt][ri * 2 + 1];
                if (mode == 0) {
                    *(float2*)(C + (size_t)m * DM + n) = make_float2(v0, v1);
                } else {
                    if (mode == 2) {
                        const int d = n & 63;   // even
                        const float inv = exp2f((float)d * -0.20762050f);
                        float sn, cs;
                        sincosf((float)m * inv, &sn, &cs);
                        const float a = v0, b = v1;
                        v0 = (a * cs - b * sn) * oscale;
                        v1 = (b * cs + a * sn) * oscale;
                    }
                    const int hh = n >> 6;
                    const int d0 = n & 63;
                    const size_t off = ((size_t)hh * SEQ + m) * DK + d0;
                    *(uint32_t*)(Ch + off) = cvt_h2(v0, v1);
                }
            }
        }
}

// ---------------------------------------------------------------------------
// FA2-style flash attention, causal, fp16 mma — fully 1-term.
// Br=128 (8 warps x 16 rows), Bc=64, 2 CTAs/SM. Q pre-scaled by 0.125*log2e.
// S = Qh·Kh. P via ex2.approx.f16x2; l via ones-column V tile in tensor core.
// Causal mask hoisted to last 2 iterations. Output single fp16.
// ---------------------------------------------------------------------------
#define F_K0  0        // 64x144B
#define F_K1  9216
#define F_V0  18432    // bytes 128..143 of each row = ones-column pad
#define F_V1  27648
#define F_Q   36864    // 128x144B
#define F_TOT 55296

__global__ void __launch_bounds__(256, 2)
flash_tc(const __half* __restrict__ qh, const __half* __restrict__ kh,
         const __half* __restrict__ vh, __half* __restrict__ aoh)
{
    extern __shared__ __align__(128) char sma[];
    const uint32_t sbase = s2u(sma);

    const int h    = blockIdx.y;
    const int qb   = gridDim.x - 1 - blockIdx.x;   // heavy tiles first
    const int tid  = threadIdx.x;
    const int lane = tid & 31;
    const int wid  = tid >> 5;
    const int wm   = wid * 16;
    const int g    = lane >> 2;
    const int tq   = lane & 3;

    const size_t hb = (size_t)h * SEQ * DK;
    const int nkb = 2 * qb + 2;     // number of 64-token blocks

    // ---- prologue: Q (group), K0+V0 (group) ----
    {
        const __half* qgh = qh + hb + (size_t)qb * 128 * DK;
#pragma unroll
        for (int i = 0; i < 4; ++i) {
            const int idx = i * 256 + tid;
            const int r = idx >> 3;
            const int c = idx & 7;
            cp16(sbase + F_Q + r * 144 + c * 16, qgh + r * 64 + c * 8);
        }
        CP_COMMIT;
        const __half* kgh = kh + hb;
        const __half* vgh = vh + hb;
#pragma unroll
        for (int i = 0; i < 2; ++i) {
            const int idx = i * 256 + tid;
            const int r = idx >> 3;        // 0..63
            const int c = idx & 7;
            cp16(sbase + F_K0 + r * 144 + c * 16, kgh + r * 64 + c * 8);
            cp16(sbase + F_V0 + r * 144 + c * 16, vgh + r * 64 + c * 8);
        }
        CP_COMMIT;
    }
    // ones-column pad for both V buffers (cp.async never touches bytes 128..143)
    if (tid < 128) {
        const int buf = tid >> 6;
        const int r = tid & 63;
        uint4* p = (uint4*)(sma + (buf ? F_V1 : F_V0) + r * 144 + 128);
        *p = make_uint4(0x00003c00u, 0u, 0u, 0u);
    }
    CP_WAIT1;
    __syncthreads();

    // ---- Q fragments (resident all kernel) ----
    uint32_t qfh[4][4];
#pragma unroll
    for (int d16 = 0; d16 < 4; ++d16) {
        const uint32_t ad = sbase + F_Q +
            ((wm + (lane & 15)) * 72 + d16 * 16 + (lane >> 4) * 8) * 2;
        ldsm4(qfh[d16], ad);
    }

    float oacc[8][4] = {};
    float oaccL[4] = {};            // ones-column accumulator: col0 = sum(p)
    float mrow[2] = { -1e30f, -1e30f };

    auto body = [&](int kb, bool domask) {
        __syncthreads();

        // prefetch K,V (kb+1)
        if (kb + 1 < nkb) {
            const __half* kgh = kh + hb + (size_t)(kb + 1) * 64 * DK;
            const __half* vgh = vh + hb + (size_t)(kb + 1) * 64 * DK;
            const uint32_t kB = sbase + (((kb + 1) & 1) ? F_K1 : F_K0);
            const uint32_t vB = sbase + (((kb + 1) & 1) ? F_V1 : F_V0);
#pragma unroll
            for (int i = 0; i < 2; ++i) {
                const int idx = i * 256 + tid;
                const int r = idx >> 3;
                const int c = idx & 7;
                cp16(kB + r * 144 + c * 16, kgh + r * 64 + c * 8);
                cp16(vB + r * 144 + c * 16, vgh + r * 64 + c * 8);
            }
        }
        CP_COMMIT;
        CP_WAIT1;
        __syncthreads();

        const uint32_t kBuf = sbase + ((kb & 1) ? F_K1 : F_K0);
        const uint32_t vBuf = sbase + ((kb & 1) ? F_V1 : F_V0);

        // ---- S = Qh · Kh (1-term) ----
        float sacc[8][4] = {};
#pragma unroll
        for (int d16 = 0; d16 < 4; ++d16) {
#pragma unroll
            for (int ng = 0; ng < 4; ++ng) {
                uint32_t bh[4];
                const uint32_t ad = kBuf +
                    ((ng * 16 + (lane & 15)) * 72 + d16 * 16 + (lane >> 4) * 8) * 2;
                ldsm4(bh, ad);
                mma16816(sacc[2 * ng],     qfh[d16], bh[0], bh[2]);
                mma16816(sacc[2 * ng + 1], qfh[d16], bh[1], bh[3]);
            }
        }

        // ---- warp-local online softmax (log2 domain), P -> half2 regs ----
        const int moff = (kb - 2 * qb) * 64;    // used only when domask
        uint32_t ph2[8][2];
        float corr[2];
#pragma unroll
        for (int hf = 0; hf < 2; ++hf) {
            const int rloc = wm + g + hf * 8;
            float vmax = -1e30f;
#pragma unroll
            for (int j = 0; j < 8; ++j)
#pragma unroll
                for (int ci = 0; ci < 2; ++ci) {
                    float v = sacc[j][hf * 2 + ci];
                    if (domask && (moff + 8 * j + 2 * tq + ci) > rloc) {
                        v = -1e30f;
                        sacc[j][hf * 2 + ci] = v;
                    }
                    vmax = fmaxf(vmax, v);
                }
            vmax = fmaxf(vmax, __shfl_xor_sync(0xffffffffu, vmax, 1));
            vmax = fmaxf(vmax, __shfl_xor_sync(0xffffffffu, vmax, 2));
            const float mnew = fmaxf(mrow[hf], vmax);
            corr[hf] = exp2f(mrow[hf] - mnew);
            mrow[hf] = mnew;
#pragma unroll
            for (int j = 0; j < 8; ++j)
                ph2[j][hf] = h2exp2(cvt_h2(sacc[j][hf * 2 + 0] - mnew,
                                           sacc[j][hf * 2 + 1] - mnew));
#pragma unroll
            for (int j = 0; j < 8; ++j) {
                oacc[j][hf * 2 + 0] *= corr[hf];
                oacc[j][hf * 2 + 1] *= corr[hf];
            }
            oaccL[hf * 2 + 0] *= corr[hf];
            oaccL[hf * 2 + 1] *= corr[hf];
        }

        // ---- O += P V ; l += P·1 (ones column) ----
#pragma unroll
        for (int kt = 0; kt < 4; ++kt) {
            uint32_t ah[4];
            ah[0] = ph2[2 * kt][0];
            ah[1] = ph2[2 * kt][1];
            ah[2] = ph2[2 * kt + 1][0];
            ah[3] = ph2[2 * kt + 1][1];
            const int t_loc = kt * 16 + (lane & 7) + ((lane >> 3) & 1) * 8;
#pragma unroll
            for (int ng = 0; ng < 4; ++ng) {
                uint32_t bh[4];
                const int d_loc = ng * 16 + ((lane >> 4) & 1) * 8;
                const uint32_t ad = vBuf + (uint32_t)(t_loc * 72 + d_loc) * 2;
                ldsm4t(bh, ad);
                mma16816(oacc[2 * ng],     ah, bh[0], bh[1]);
                mma16816(oacc[2 * ng + 1], ah, bh[2], bh[3]);
            }
            {
                uint32_t bo[2];
                ldsm2t(bo, vBuf + (uint32_t)(t_loc * 72 + 64) * 2);
                mma16816(oaccL, ah, bo[0], bo[1]);
            }
        }
    };

    for (int kb = 0; kb < nkb - 2; ++kb) body(kb, false);
    body(nkb - 2, true);
    body(nkb - 1, true);

    // ---- epilogue: l from ones-column, single fp16 output ----
#pragma unroll
    for (int hf = 0; hf < 2; ++hf) {
        const float lv = __shfl_sync(0xffffffffu, oaccL[hf * 2 + 0], lane & ~3);
        const float inv = 1.f / lv;
        const int q = qb * 128 + wm + g + hf * 8;
#pragma unroll
        for (int j = 0; j < 8; ++j) {
            const float v0 = oacc[j][hf * 2 + 0] * inv;
            const float v1 = oacc[j][hf * 2 + 1] * inv;
            const int col = h * 64 + 8 * j + 2 * tq;
            *(uint32_t*)(aoh + (size_t)q * DM + col) = cvt_h2(v0, v1);
        }
    }
}

// ---------------------------------------------------------------------------
extern "C" void kernel_launch(void* const* d_in, const int* in_sizes, int n_in,
                              void* d_out, int out_size)
{
    const float* x  = (const float*)d_in[0];
    const float* Wq = (const float*)d_in[1];
    const float* Wk = (const float*)d_in[2];
    const float* Wv = (const float*)d_in[3];
    const float* Wo = (const float*)d_in[4];

    __half *xh, *wh, *qhp, *khp, *vhp, *aoh;
    cudaGetSymbolAddress((void**)&xh,  g_xh);
    cudaGetSymbolAddress((void**)&wh,  g_wh);
    cudaGetSymbolAddress((void**)&qhp, g_qh);
    cudaGetSymbolAddress((void**)&khp, g_kh);
    cudaGetSymbolAddress((void**)&vhp, g_vh);
    cudaGetSymbolAddress((void**)&aoh, g_aoh);

    const int nx2 = SEQ * DM / 2;
    const int nw2 = DM * DM / 2;
    cvt_f16<<<(nx2 + 255) / 256, 256>>>(x, xh, nx2);
    cvt4_f16<<<dim3((nw2 + 255) / 256, 4), 256>>>(Wq, Wk, Wv, Wo, wh, nw2);

    const int gsm = 2 * 2 * 10240;   // 40,960 B
    cudaFuncSetAttribute(gemm_mma, cudaFuncAttributeMaxDynamicSharedMemorySize, gsm);
    cudaFuncSetAttribute(flash_tc, cudaFuncAttributeMaxDynamicSharedMemorySize, F_TOT);

    // fused Q/K/V projections (Q pre-scaled by 0.125*log2e)
    gemm_mma<<<dim3(DM / 128, SEQ / 128, 3), 256, gsm>>>(
        xh, wh, nullptr, qhp, khp, vhp, 1);

    flash_tc<<<dim3(SEQ / 128, NH), 256, F_TOT>>>(qhp, khp, vhp, aoh);

    // Wo projection (fp32 out)
    gemm_mma<<<dim3(DM / 128, SEQ / 128, 1), 256, gsm>>>(
        aoh, wh, (float*)d_out, nullptr, nullptr, nullptr, 0);
}

// round 17
// speedup vs baseline: 1.9027x; 1.0087x over previous
#include <cuda_runtime.h>
#include <cuda_fp16.h>
#include <math.h>
#include <stdint.h>

#define SEQ 4096
#define DM  1024
#define NH  16
#define DK  64

// ---------------------------------------------------------------------------
// scratch (no allocs allowed) — everything plain fp16
// ---------------------------------------------------------------------------
__device__ __half g_xh [SEQ * DM];
__device__ __half g_wh [4][DM * DM];
__device__ __half g_qh [NH * SEQ * DK];
__device__ __half g_kh [NH * SEQ * DK];
__device__ __half g_vh [NH * SEQ * DK];
__device__ __half g_aoh[SEQ * DM];

// ---------------------------------------------------------------------------
// helpers
// ---------------------------------------------------------------------------
static __device__ __forceinline__ uint32_t s2u(const void* p) {
    uint32_t a;
    asm("{ .reg .u64 t; cvta.to.shared.u64 t, %1; cvt.u32.u64 %0, t; }"
        : "=r"(a) : "l"(p));
    return a;
}
static __device__ __forceinline__ void ldsm4(uint32_t* r, uint32_t addr) {
    asm volatile("ldmatrix.sync.aligned.m8n8.x4.shared.b16 {%0,%1,%2,%3}, [%4];"
                 : "=r"(r[0]), "=r"(r[1]), "=r"(r[2]), "=r"(r[3]) : "r"(addr));
}
static __device__ __forceinline__ void ldsm4t(uint32_t* r, uint32_t addr) {
    asm volatile("ldmatrix.sync.aligned.m8n8.x4.trans.shared.b16 {%0,%1,%2,%3}, [%4];"
                 : "=r"(r[0]), "=r"(r[1]), "=r"(r[2]), "=r"(r[3]) : "r"(addr));
}
static __device__ __forceinline__ void ldsm2t(uint32_t* r, uint32_t addr) {
    asm volatile("ldmatrix.sync.aligned.m8n8.x2.trans.shared.b16 {%0,%1}, [%2];"
                 : "=r"(r[0]), "=r"(r[1]) : "r"(addr));
}
static __device__ __forceinline__ void mma16816(float* d, const uint32_t* a,
                                                uint32_t b0, uint32_t b1) {
    asm volatile(
        "mma.sync.aligned.m16n8k16.row.col.f32.f16.f16.f32 "
        "{%0,%1,%2,%3},{%4,%5,%6,%7},{%8,%9},{%0,%1,%2,%3};"
        : "+f"(d[0]), "+f"(d[1]), "+f"(d[2]), "+f"(d[3])
        : "r"(a[0]), "r"(a[1]), "r"(a[2]), "r"(a[3]), "r"(b0), "r"(b1));
}
static __device__ __forceinline__ void cp16(uint32_t s, const void* g) {
    asm volatile("cp.async.cg.shared.global [%0], [%1], 16;" :: "r"(s), "l"(g));
}
#define CP_COMMIT asm volatile("cp.async.commit_group;")
#define CP_WAIT1  asm volatile("cp.async.wait_group 1;")
#define CP_WAIT2  asm volatile("cp.async.wait_group 2;")

static __device__ __forceinline__ uint32_t cvt_h2(float lo, float hi) {
    uint32_t r;
    asm("cvt.rn.f16x2.f32 %0, %1, %2;" : "=r"(r) : "f"(hi), "f"(lo));
    return r;
}
static __device__ __forceinline__ uint32_t h2exp2(uint32_t x) {
    uint32_t r;
    asm("ex2.approx.f16x2 %0, %1;" : "=r"(r) : "r"(x));
    return r;
}

// ---------------------------------------------------------------------------
// converts
// ---------------------------------------------------------------------------
__global__ void __launch_bounds__(256)
cvt_f16(const float* __restrict__ src, __half* __restrict__ dst, int n2)
{
    int i = blockIdx.x * 256 + threadIdx.x;
    if (i >= n2) return;
    float2 v = ((const float2*)src)[i];
    ((uint32_t*)dst)[i] = cvt_h2(v.x, v.y);
}

__global__ void __launch_bounds__(256)
cvt4_f16(const float* __restrict__ s0, const float* __restrict__ s1,
         const float* __restrict__ s2, const float* __restrict__ s3,
         __half* __restrict__ dst, int n2)
{
    int i = blockIdx.x * 256 + threadIdx.x;
    if (i >= n2) return;
    const int y = blockIdx.y;
    const float* s = (y == 0) ? s0 : (y == 1) ? s1 : (y == 2) ? s2 : s3;
    float2 v = ((const float2*)s)[i];
    ((uint32_t*)dst)[(size_t)y * (DM * DM / 2) + i] = cvt_h2(v.x, v.y);
}

// ---------------------------------------------------------------------------
// mma.sync fp16 GEMM: C = A · B^T. 128x128x32 tiles, 3-stage cp.async
// pipeline (ONE sync per k-chunk), 8 warps (2m x 4n), 2 CTAs/SM.
// qkv!=0: z selects weight; z==0 scaled by 0.125*log2e + RoPE+head;
// z==1 RoPE+head; z==2 head. qkv==0: fp32 out with weight 3 (Wo).
// ---------------------------------------------------------------------------
__global__ void __launch_bounds__(256, 2)
gemm_mma(const __half* __restrict__ A_g, const __half* __restrict__ WhAll,
         float* __restrict__ C,
         __half* __restrict__ C0h, __half* __restrict__ C1h, __half* __restrict__ C2h,
         int qkv)
{
    constexpr int K = DM;
    constexpr int NKC = K / 32;
    constexpr int TILE  = 10240;   // 128 rows x 40 fp16 (pitch 80B)
    constexpr int STAGE = 2 * TILE;
    extern __shared__ __align__(128) char smg[];
    const uint32_t sbase = s2u(smg);

    const int z   = blockIdx.z;
    const int mode = qkv ? ((z == 2) ? 1 : 2) : 0;
    const float oscale = (qkv && z == 0) ? 0.125f * 1.44269504f : 1.0f;
    const size_t wsel = qkv ? (size_t)z * DM * DM : (size_t)3 * DM * DM;
    const __half* B_g = WhAll + wsel;
    __half* Ch = (z == 0) ? C0h : (z == 1) ? C1h : C2h;

    const int bm  = blockIdx.y * 128;
    const int bn  = blockIdx.x * 128;
    const int tid = threadIdx.x;
    const int lane = tid & 31;
    const int wid  = tid >> 5;
    const int wm = (wid >> 2) * 64;
    const int wn = (wid & 3) * 32;

    const __half* srcs[2] = { A_g + (size_t)bm * K, B_g + (size_t)bn * K };

    auto fill = [&](int s, int kc) {
#pragma unroll
        for (int t = 0; t < 2; ++t) {
#pragma unroll
            for (int i = 0; i < 2; ++i) {
                const int idx = i * 256 + tid;
                const int r = idx >> 2;
                const int c = idx & 3;
                cp16(sbase + s * STAGE + t * TILE + r * 80 + c * 16,
                     srcs[t] + (size_t)r * K + kc * 32 + c * 8);
            }
        }
        CP_COMMIT;
    };

    float acc[4][4][4] = {};

    fill(0, 0);
    fill(1, 1);
    int stage = 0;
    for (int kc = 0; kc < NKC; ++kc) {
        CP_WAIT1;          // stage kc resident (kc+1 may pend)
        __syncthreads();   // all warps done with stage (kc+2)%3 reads (iter kc-1)
        if (kc + 2 < NKC) fill((stage + 2) % 3, kc + 2);

        const uint32_t aB = sbase + stage * STAGE;
        const uint32_t bB = aB + TILE;
#pragma unroll
        for (int ks = 0; ks < 2; ++ks) {
            uint32_t ah[4][4];
#pragma unroll
            for (int mt = 0; mt < 4; ++mt) {
                const uint32_t ad = aB +
                    ((wm + mt * 16 + (lane & 15)) * 40 + ks * 16 + (lane >> 4) * 8) * 2;
                ldsm4(ah[mt], ad);
            }
#pragma unroll
            for (int np = 0; np < 2; ++np) {
                uint32_t bh[4];
                const uint32_t ad = bB +
                    ((wn + np * 16 + (lane & 15)) * 40 + ks * 16 + (lane >> 4) * 8) * 2;
                ldsm4(bh, ad);
#pragma unroll
                for (int mt = 0; mt < 4; ++mt)
#pragma unroll
                    for (int hf = 0; hf < 2; ++hf)
                        mma16816(acc[mt][np * 2 + hf], ah[mt], bh[hf], bh[hf + 2]);
            }
        }
        stage = (stage + 1) % 3;
    }

#pragma unroll
    for (int mt = 0; mt < 4; ++mt)
#pragma unroll
        for (int ri = 0; ri < 2; ++ri) {
            const int m = bm + wm + mt * 16 + ri * 8 + (lane >> 2);
#pragma unroll
            for (int nt = 0; nt < 4; ++nt) {
                const int n = bn + wn + nt * 8 + 2 * (lane & 3);
                float v0 = acc[mt][nt][ri * 2 + 0];
                float v1 = acc[mt][nt][ri * 2 + 1];
                if (mode == 0) {
                    *(float2*)(C + (size_t)m * DM + n) = make_float2(v0, v1);
                } else {
                    if (mode == 2) {
                        const int d = n & 63;   // even
                        const float inv = exp2f((float)d * -0.20762050f);
                        float sn, cs;
                        sincosf((float)m * inv, &sn, &cs);
                        const float a = v0, b = v1;
                        v0 = (a * cs - b * sn) * oscale;
                        v1 = (b * cs + a * sn) * oscale;
                    }
                    const int hh = n >> 6;
                    const int d0 = n & 63;
                    const size_t off = ((size_t)hh * SEQ + m) * DK + d0;
                    *(uint32_t*)(Ch + off) = cvt_h2(v0, v1);
                }
            }
        }
}

// ---------------------------------------------------------------------------
// FA2-style flash attention, causal, fp16 mma — 1-term, 3-stage K/V pipeline
// (ONE sync per 64-token block). Br=128 (8 warps x 16 rows), Bc=64,
// 2 CTAs/SM. Q pre-scaled by 0.125*log2e; P via ex2.approx.f16x2;
// l via constant ones-column fragment (hoisted) in the tensor core.
// Causal mask hoisted to last 2 iterations. Output single fp16.
// ---------------------------------------------------------------------------
#define F_KV(s) ((s) * 18432)          // K at +0 (64x144B), V at +9216
#define F_Q     55296                  // 128x144B
#define F_TOT   73728

__global__ void __launch_bounds__(256, 2)
flash_tc(const __half* __restrict__ qh, const __half* __restrict__ kh,
         const __half* __restrict__ vh, __half* __restrict__ aoh)
{
    extern __shared__ __align__(128) char sma[];
    const uint32_t sbase = s2u(sma);

    const int h    = blockIdx.y;
    const int qb   = gridDim.x - 1 - blockIdx.x;   // heavy tiles first
    const int tid  = threadIdx.x;
    const int lane = tid & 31;
    const int wid  = tid >> 5;
    const int wm   = wid * 16;
    const int g    = lane >> 2;
    const int tq   = lane & 3;

    const size_t hb = (size_t)h * SEQ * DK;
    const int nkb = 2 * qb + 2;     // number of 64-token blocks

    auto fill_kv = [&](int s, int kb) {
        const __half* kg = kh + hb + (size_t)kb * 64 * DK;
        const __half* vg = vh + hb + (size_t)kb * 64 * DK;
        const uint32_t base = sbase + F_KV(s);
#pragma unroll
        for (int i = 0; i < 2; ++i) {
            const int idx = i * 256 + tid;
            const int r = idx >> 3;        // 0..63
            const int c = idx & 7;
            cp16(base + r * 144 + c * 16, kg + r * 64 + c * 8);
            cp16(base + 9216 + r * 144 + c * 16, vg + r * 64 + c * 8);
        }
        CP_COMMIT;
    };

    // ---- prologue: Q (group), KV0, KV1 (groups); ones pads ----
    {
        const __half* qgh = qh + hb + (size_t)qb * 128 * DK;
#pragma unroll
        for (int i = 0; i < 4; ++i) {
            const int idx = i * 256 + tid;
            const int r = idx >> 3;
            const int c = idx & 7;
            cp16(sbase + F_Q + r * 144 + c * 16, qgh + r * 64 + c * 8);
        }
        CP_COMMIT;
    }
    fill_kv(0, 0);
    fill_kv(1, 1);   // nkb >= 2 always
    // ones-column pad for all 3 V buffers (cp.async never touches bytes 128..143)
    if (tid < 192) {
        const int s = tid >> 6;
        const int r = tid & 63;
        uint4* p = (uint4*)(sma + F_KV(s) + 9216 + r * 144 + 128);
        *p = make_uint4(0x00003c00u, 0u, 0u, 0u);
    }
    CP_WAIT2;          // Q resident (KV0/KV1 may pend)
    __syncthreads();

    // ---- Q fragments + constant ones-column B-fragment ----
    uint32_t qfh[4][4];
#pragma unroll
    for (int d16 = 0; d16 < 4; ++d16) {
        const uint32_t ad = sbase + F_Q +
            ((wm + (lane & 15)) * 72 + d16 * 16 + (lane >> 4) * 8) * 2;
        ldsm4(qfh[d16], ad);
    }
    uint32_t bo_const[2];
    {
        const int t_loc = (lane & 7) + ((lane >> 3) & 1) * 8;
        ldsm2t(bo_const, sbase + F_KV(0) + 9216 + (uint32_t)(t_loc * 72 + 64) * 2);
    }

    float oacc[8][4] = {};
    float oaccL[4] = {};            // ones-column accumulator: col0 = sum(p)
    float mrow[2] = { -1e30f, -1e30f };

    int stage = 0;
    auto body = [&](int kb, bool domask) {
        CP_WAIT1;          // KV(kb) resident (KV(kb+1) may pend)
        __syncthreads();   // all warps done reading stage (kb+2)%3 (iter kb-1)
        if (kb + 2 < nkb) fill_kv((stage + 2) % 3, kb + 2);

        const uint32_t kBuf = sbase + F_KV(stage);
        const uint32_t vBuf = kBuf + 9216;

        // ---- S = Qh · Kh ----
        float sacc[8][4] = {};
#pragma unroll
        for (int d16 = 0; d16 < 4; ++d16) {
#pragma unroll
            for (int ng = 0; ng < 4; ++ng) {
                uint32_t bh[4];
                const uint32_t ad = kBuf +
                    ((ng * 16 + (lane & 15)) * 72 + d16 * 16 + (lane >> 4) * 8) * 2;
                ldsm4(bh, ad);
                mma16816(sacc[2 * ng],     qfh[d16], bh[0], bh[2]);
                mma16816(sacc[2 * ng + 1], qfh[d16], bh[1], bh[3]);
            }
        }

        // ---- warp-local online softmax (log2 domain), P -> half2 regs ----
        const int moff = (kb - 2 * qb) * 64;    // used only when domask
        uint32_t ph2[8][2];
        float corr[2];
#pragma unroll
        for (int hf = 0; hf < 2; ++hf) {
            const int rloc = wm + g + hf * 8;
            float vmax = -1e30f;
#pragma unroll
            for (int j = 0; j < 8; ++j)
#pragma unroll
                for (int ci = 0; ci < 2; ++ci) {
                    float v = sacc[j][hf * 2 + ci];
                    if (domask && (moff + 8 * j + 2 * tq + ci) > rloc) {
                        v = -1e30f;
                        sacc[j][hf * 2 + ci] = v;
                    }
                    vmax = fmaxf(vmax, v);
                }
            vmax = fmaxf(vmax, __shfl_xor_sync(0xffffffffu, vmax, 1));
            vmax = fmaxf(vmax, __shfl_xor_sync(0xffffffffu, vmax, 2));
            const float mnew = fmaxf(mrow[hf], vmax);
            corr[hf] = exp2f(mrow[hf] - mnew);
            mrow[hf] = mnew;
#pragma unroll
            for (int j = 0; j < 8; ++j)
                ph2[j][hf] = h2exp2(cvt_h2(sacc[j][hf * 2 + 0] - mnew,
                                           sacc[j][hf * 2 + 1] - mnew));
#pragma unroll
            for (int j = 0; j < 8; ++j) {
                oacc[j][hf * 2 + 0] *= corr[hf];
                oacc[j][hf * 2 + 1] *= corr[hf];
            }
            oaccL[hf * 2 + 0] *= corr[hf];
            oaccL[hf * 2 + 1] *= corr[hf];
        }

        // ---- O += P V ; l += P·1 (constant ones fragment) ----
#pragma unroll
        for (int kt = 0; kt < 4; ++kt) {
            uint32_t ah[4];
            ah[0] = ph2[2 * kt][0];
            ah[1] = ph2[2 * kt][1];
            ah[2] = ph2[2 * kt + 1][0];
            ah[3] = ph2[2 * kt + 1][1];
            const int t_loc = kt * 16 + (lane & 7) + ((lane >> 3) & 1) * 8;
#pragma unroll
            for (int ng = 0; ng < 4; ++ng) {
                uint32_t bh[4];
                const int d_loc = ng * 16 + ((lane >> 4) & 1) * 8;
                const uint32_t ad = vBuf + (uint32_t)(t_loc * 72 + d_loc) * 2;
                ldsm4t(bh, ad);
                mma16816(oacc[2 * ng],     ah, bh[0], bh[1]);
                mma16816(oacc[2 * ng + 1], ah, bh[2], bh[3]);
            }
            mma16816(oaccL, ah, bo_const[0], bo_const[1]);
        }
        stage = (stage + 1) % 3;
    };

    for (int kb = 0; kb < nkb - 2; ++kb) body(kb, false);
    body(nkb - 2, true);
    body(nkb - 1, true);

    // ---- epilogue: l from ones-column, single fp16 output ----
#pragma unroll
    for (int hf = 0; hf < 2; ++hf) {
        const float lv = __shfl_sync(0xffffffffu, oaccL[hf * 2 + 0], lane & ~3);
        const float inv = 1.f / lv;
        const int q = qb * 128 + wm + g + hf * 8;
#pragma unroll
        for (int j = 0; j < 8; ++j) {
            const float v0 = oacc[j][hf * 2 + 0] * inv;
            const float v1 = oacc[j][hf * 2 + 1] * inv;
            const int col = h * 64 + 8 * j + 2 * tq;
            *(uint32_t*)(aoh + (size_t)q * DM + col) = cvt_h2(v0, v1);
        }
    }
}

// ---------------------------------------------------------------------------
extern "C" void kernel_launch(void* const* d_in, const int* in_sizes, int n_in,
                              void* d_out, int out_size)
{
    const float* x  = (const float*)d_in[0];
    const float* Wq = (const float*)d_in[1];
    const float* Wk = (const float*)d_in[2];
    const float* Wv = (const float*)d_in[3];
    const float* Wo = (const float*)d_in[4];

    __half *xh, *wh, *qhp, *khp, *vhp, *aoh;
    cudaGetSymbolAddress((void**)&xh,  g_xh);
    cudaGetSymbolAddress((void**)&wh,  g_wh);
    cudaGetSymbolAddress((void**)&qhp, g_qh);
    cudaGetSymbolAddress((void**)&khp, g_kh);
    cudaGetSymbolAddress((void**)&vhp, g_vh);
    cudaGetSymbolAddress((void**)&aoh, g_aoh);

    const int nx2 = SEQ * DM / 2;
    const int nw2 = DM * DM / 2;
    cvt_f16<<<(nx2 + 255) / 256, 256>>>(x, xh, nx2);
    cvt4_f16<<<dim3((nw2 + 255) / 256, 4), 256>>>(Wq, Wk, Wv, Wo, wh, nw2);

    const int gsm = 3 * 2 * 10240;   // 61,440 B (3-stage)
    cudaFuncSetAttribute(gemm_mma, cudaFuncAttributeMaxDynamicSharedMemorySize, gsm);
    cudaFuncSetAttribute(flash_tc, cudaFuncAttributeMaxDynamicSharedMemorySize, F_TOT);

    // fused Q/K/V projections (Q pre-scaled by 0.125*log2e)
    gemm_mma<<<dim3(DM / 128, SEQ / 128, 3), 256, gsm>>>(
        xh, wh, nullptr, qhp, khp, vhp, 1);

    flash_tc<<<dim3(SEQ / 128, NH), 256, F_TOT>>>(qhp, khp, vhp, aoh);

    // Wo projection (fp32 out)
    gemm_mma<<<dim3(DM / 128, SEQ / 128, 1), 256, gsm>>>(
        aoh, wh, (float*)d_out, nullptr, nullptr, nullptr, 0);
}